// round 8
// baseline (speedup 1.0000x reference)
#include <cuda_runtime.h>
#include <math.h>

typedef unsigned int u32;
typedef unsigned short u16;

#define NN 200000
#define DD 128
#define G3 384
#define MD 12
#define NT32 (NN / 32)                // 6250 exact
#define RB ((NN + 255) / 256)         // 782

// smem layout: A tile 32x264u16 | B tile 128x264u16 | bias 4x128 f32
#define SM_A 0
#define SM_B 16896
#define SM_BIAS 84480
#define SMT 86528
#define LDS_ROW 528                   // 264 u16 = 528 bytes per smem row

// ---------------- scratch (device globals: allocation-free) ----------------
__device__ __align__(256) float g_gi[(size_t)NN * G3];    // x@W_ih^T (no bias)
__device__ __align__(256) u16 g_xs[(size_t)NN * 256];     // x split: [hi 128 | lo 128] bf16
__device__ __align__(256) u16 g_hs[(size_t)NN * 256];     // h split (permuted order)
__device__ __align__(256) u16 g_wih2[384 * 256];
__device__ __align__(256) u16 g_whh2[384 * 256];
__device__ __align__(256) u16 g_wself2[128 * 256];
__device__ __align__(256) u16 g_wneigh2[128 * 256];
__device__ float g_psum[RB * DD];
__device__ float g_psq [RB * DD];
__device__ float g_a[DD], g_b[DD];
__device__ int   g_cnt[MD + 1], g_cur[MD + 1], g_act[MD];
__device__ int   g_perm[NN];
__device__ int   g_mtype;

__device__ __forceinline__ float sigm(float x) { return 1.0f / (1.0f + expf(-x)); }

// bf16 split helpers (bit-level, RNE)
__device__ __forceinline__ u32 bf_rn(float v, float& asf) {
    u32 u = __float_as_uint(v);
    u32 r = (u + 0x7FFFu + ((u >> 16) & 1u)) & 0xFFFF0000u;
    asf = __uint_as_float(r);
    return r >> 16;
}
__device__ __forceinline__ float bf2f_lo(u32 w) { return __uint_as_float(w << 16); }
__device__ __forceinline__ float bf2f_hi(u32 w) { return __uint_as_float(w & 0xFFFF0000u); }

__device__ __forceinline__ u32 su32(const void* p) {
    return (u32)__cvta_generic_to_shared(p);
}
__device__ __forceinline__ void ldsm4(u32& r0, u32& r1, u32& r2, u32& r3, u32 a) {
    asm volatile("ldmatrix.sync.aligned.m8n8.x4.shared.b16 {%0,%1,%2,%3}, [%4];"
                 : "=r"(r0), "=r"(r1), "=r"(r2), "=r"(r3) : "r"(a));
}
__device__ __forceinline__ void mma_bf16(float* c, u32 a0, u32 a1, u32 a2, u32 a3,
                                         u32 b0, u32 b1) {
    asm volatile("mma.sync.aligned.m16n8k16.row.col.f32.bf16.bf16.f32 "
                 "{%0,%1,%2,%3}, {%4,%5,%6,%7}, {%8,%9}, {%0,%1,%2,%3};"
                 : "+f"(c[0]), "+f"(c[1]), "+f"(c[2]), "+f"(c[3])
                 : "r"(a0), "r"(a1), "r"(a2), "r"(a3), "r"(b0), "r"(b1));
}

// one warp-level GEMM pass: A[32x256 split] x B[128x256 split]^T -> acc[4][4]
// warp wm (0/1): rows wm*16..+16; warp wn (0..3): cols wn*32..+32 (4 n-tiles of 8)
// 3 products: hi*hi, lo*hi, hi*lo  (K=128 each, 8 k16 steps)
__device__ __forceinline__ void gemm_pass(u32 As, u32 Bs, int lane, int wm, int wn,
                                          float acc[4][4]) {
    u32 aRow  = As + (u32)((wm * 16 + (lane & 15)) * LDS_ROW + (lane >> 4) * 16);
    u32 bRow0 = Bs + (u32)((wn * 32 + ((lane >> 4) << 3) + (lane & 7)) * LDS_ROW
                           + ((lane >> 3) & 1) * 16);
    u32 bRow1 = bRow0 + 16 * LDS_ROW;
#pragma unroll
    for (int p = 0; p < 3; ++p) {
        int aK = (p == 1) ? 256 : 0;      // byte offset (128 elems * 2B)
        int bK = (p == 2) ? 256 : 0;
#pragma unroll
        for (int s = 0; s < 8; ++s) {
            u32 a0, a1, a2, a3, b0, b1, b2, b3;
            ldsm4(a0, a1, a2, a3, aRow + aK + 32 * s);
            ldsm4(b0, b1, b2, b3, bRow0 + bK + 32 * s);
            mma_bf16(acc[0], a0, a1, a2, a3, b0, b1);
            mma_bf16(acc[1], a0, a1, a2, a3, b2, b3);
            ldsm4(b0, b1, b2, b3, bRow1 + bK + 32 * s);
            mma_bf16(acc[2], a0, a1, a2, a3, b0, b1);
            mma_bf16(acc[3], a0, a1, a2, a3, b2, b3);
        }
    }
}

// tile loaders: rows of 256 u16 -> smem rows of 264 u16 (528B stride)
__device__ __forceinline__ void ldA32(char* dst, const u16* __restrict__ g,
                                      int rbase, int tid) {
#pragma unroll
    for (int it = 0; it < 4; ++it) {
        int idx = tid + it * 256;
        int r = idx >> 5, c = idx & 31;
        uint4 v = ((const uint4*)g)[(size_t)(rbase + r) * 32 + c];
        *(uint4*)(dst + r * LDS_ROW + c * 16) = v;
    }
}
__device__ __forceinline__ void ldA32_g(char* dst, const u16* __restrict__ g,
                                        const int* __restrict__ perm, int base, int tid) {
#pragma unroll
    for (int it = 0; it < 4; ++it) {
        int idx = tid + it * 256;
        int r = idx >> 5, c = idx & 31;
        int row = perm[base + r];
        uint4 v = ((const uint4*)g)[(size_t)row * 32 + c];
        *(uint4*)(dst + r * LDS_ROW + c * 16) = v;
    }
}
__device__ __forceinline__ void ldB128(char* dst, const u16* __restrict__ g, int tid) {
#pragma unroll
    for (int it = 0; it < 16; ++it) {
        int idx = tid + it * 256;
        int r = idx >> 5, c = idx & 31;
        uint4 v = ((const uint4*)g)[(size_t)r * 32 + c];
        *(uint4*)(dst + r * LDS_ROW + c * 16) = v;
    }
}

// ---------------- mask dtype detection / setup (verified passing in R6) ----------------
__global__ void k_detect(const unsigned char* __restrict__ m) {
    __shared__ int has3F, nzNot0, nz0;
    if (threadIdx.x == 0) { has3F = 0; nzNot0 = 0; nz0 = 0; }
    __syncthreads();
    for (int i = threadIdx.x; i < 16384; i += 256) {
        unsigned char b = m[i];
        if (b == 0x3F) atomicOr(&has3F, 1);
        if (b != 0 && (i & 3) != 0) atomicOr(&nzNot0, 1);
        if (b != 0 && (i & 3) == 0) atomicOr(&nz0, 1);
    }
    __syncthreads();
    if (threadIdx.x == 0) {
        int ty;
        if (has3F && nz0) ty = 3;
        else if (has3F)   ty = 2;
        else if (nzNot0)  ty = 0;
        else              ty = 1;
        g_mtype = ty;
    }
}

__device__ __forceinline__ int deg_any(const void* m, int n) {
    int ty = g_mtype;
    int d = 0;
    if (ty == 1) {
        const int* p = (const int*)m + (size_t)n * MD;
#pragma unroll
        for (int j = 0; j < MD; ++j) d += (p[j] != 0);
    } else if (ty == 0) {
        const unsigned char* p = (const unsigned char*)m + (size_t)n * MD;
#pragma unroll
        for (int j = 0; j < MD; ++j) d += (p[j] != 0);
    } else if (ty == 2) {
        const float* p = (const float*)m + (size_t)n * MD;
#pragma unroll
        for (int j = 0; j < MD; ++j) d += (p[j] != 0.0f);
    } else {
        const u16* p = (const u16*)m + (size_t)n * MD;
#pragma unroll
        for (int j = 0; j < MD; ++j) d += ((p[j] & 0x7FFF) != 0);
    }
    return d;
}

__global__ void k_zero() { int t = threadIdx.x; if (t <= MD) g_cnt[t] = 0; }

__global__ void k_stats(const float* __restrict__ feat) {
    int col = threadIdx.x;
    int r0 = blockIdx.x * 256;
    int rend = min(r0 + 256, NN);
    float s = 0.f, q = 0.f;
    for (int r = r0; r < rend; ++r) {
        float v = feat[(size_t)r * DD + col];
        s += v; q += v * v;
    }
    g_psum[blockIdx.x * DD + col] = s;
    g_psq [blockIdx.x * DD + col] = q;
}

__global__ void k_deg(const void* __restrict__ mask) {
    __shared__ int c[MD + 1];
    int tid = threadIdx.x;
    if (tid <= MD) c[tid] = 0;
    __syncthreads();
    int n = blockIdx.x * 256 + tid;
    if (n < NN) atomicAdd(&c[deg_any(mask, n)], 1);
    __syncthreads();
    if (tid <= MD && c[tid] > 0) atomicAdd(&g_cnt[tid], c[tid]);
}

__global__ void k_finalize(const float* __restrict__ gamma, const float* __restrict__ beta) {
    int t = threadIdx.x;
    float s = 0.f, q = 0.f;
    for (int b = 0; b < RB; ++b) { s += g_psum[b * DD + t]; q += g_psq[b * DD + t]; }
    float mu = s * (1.0f / NN);
    float var = q * (1.0f / NN) - mu * mu;
    float rs = rsqrtf(var + 1e-5f);
    float a = rs * gamma[t];
    g_a[t] = a;
    g_b[t] = beta[t] - mu * a;
    if (t == 0) {
        int suf = 0;
        for (int d = MD; d >= 0; --d) { g_cur[d] = suf; suf += g_cnt[d]; }
        for (int sdx = 0; sdx < MD; ++sdx) g_act[sdx] = g_cur[sdx];
    }
}

__global__ void k_scatter(const void* __restrict__ mask) {
    int n = blockIdx.x * 256 + threadIdx.x;
    if (n >= NN) return;
    int pos = atomicAdd(&g_cur[deg_any(mask, n)], 1);
    g_perm[pos] = n;
}

// normalize + bf16 split -> g_xs
__global__ void k_normsplit(const float* __restrict__ feat) {
    int i = blockIdx.x * 256 + threadIdx.x;
    if (i >= NN * DD / 4) return;
    float4 v = ((const float4*)feat)[i];
    int row = i >> 5;
    int c = (i & 31) << 2;
    float f0 = v.x * g_a[c + 0] + g_b[c + 0];
    float f1 = v.y * g_a[c + 1] + g_b[c + 1];
    float f2 = v.z * g_a[c + 2] + g_b[c + 2];
    float f3 = v.w * g_a[c + 3] + g_b[c + 3];
    float h0, h1, h2, h3, d0, d1, d2, d3;
    u32 a0 = bf_rn(f0, h0), a1 = bf_rn(f1, h1), a2 = bf_rn(f2, h2), a3 = bf_rn(f3, h3);
    u32 b0 = bf_rn(f0 - h0, d0), b1 = bf_rn(f1 - h1, d1), b2 = bf_rn(f2 - h2, d2), b3 = bf_rn(f3 - h3, d3);
    u16* dst = g_xs + (size_t)row * 256;
    *(uint2*)(dst + c)       = make_uint2(a0 | (a1 << 16), a2 | (a3 << 16));
    *(uint2*)(dst + 128 + c) = make_uint2(b0 | (b1 << 16), b2 | (b3 << 16));
}

// weight conversion: 1024 rows (384 Wih, 384 Whh, 128 Wself, 128 Wneigh)
__global__ void k_wsplit(const float* __restrict__ wih, const float* __restrict__ whh,
                         const float* __restrict__ wself, const float* __restrict__ wneigh) {
    int i = blockIdx.x * 256 + threadIdx.x;
    int row = i >> 5;
    int c = (i & 31) << 2;
    const float* src;
    u16* dst;
    if (row < 384)      { src = wih + (size_t)row * 128;           dst = g_wih2 + (size_t)row * 256; }
    else if (row < 768) { src = whh + (size_t)(row - 384) * 128;   dst = g_whh2 + (size_t)(row - 384) * 256; }
    else if (row < 896) { src = wself + (size_t)(row - 768) * 128; dst = g_wself2 + (size_t)(row - 768) * 256; }
    else                { src = wneigh + (size_t)(row - 896) * 128; dst = g_wneigh2 + (size_t)(row - 896) * 256; }
    float4 v = *(const float4*)(src + c);
    float h0, h1, h2, h3, dm;
    u32 a0 = bf_rn(v.x, h0), a1 = bf_rn(v.y, h1), a2 = bf_rn(v.z, h2), a3 = bf_rn(v.w, h3);
    u32 b0 = bf_rn(v.x - h0, dm), b1 = bf_rn(v.y - h1, dm), b2 = bf_rn(v.z - h2, dm), b3 = bf_rn(v.w - h3, dm);
    *(uint2*)(dst + c)       = make_uint2(a0 | (a1 << 16), a2 | (a3 << 16));
    *(uint2*)(dst + 128 + c) = make_uint2(b0 | (b1 << 16), b2 | (b3 << 16));
}

// ---------------- GEMM: gi = x @ W_ih^T (no bias), all N rows ----------------
__global__ void __launch_bounds__(256) k_gi_mm() {
    extern __shared__ char sm[];
    int tid = threadIdx.x, lane = tid & 31, wid = tid >> 5;
    int wm = wid >> 2, wn = wid & 3;
    int tile = blockIdx.x;
    ldA32(sm + SM_A, g_xs, tile * 32, tid);
    u32 As = su32(sm + SM_A), Bs = su32(sm + SM_B);
    float acc[3][4][4] = {};
#pragma unroll 1
    for (int g = 0; g < 3; ++g) {
        __syncthreads();
        ldB128(sm + SM_B, g_wih2 + (size_t)g * 128 * 256, tid);
        __syncthreads();
        gemm_pass(As, Bs, lane, wm, wn, acc[g]);
    }
    int qr = lane >> 2, qc = (lane & 3) * 2;
#pragma unroll
    for (int e = 0; e < 2; ++e) {
        int R = tile * 32 + wm * 16 + qr + 8 * e;
        float* dst = g_gi + (size_t)R * G3;
#pragma unroll
        for (int g = 0; g < 3; ++g)
#pragma unroll
        for (int nt = 0; nt < 4; ++nt) {
            int col = wn * 32 + nt * 8 + qc;
            *(float2*)(dst + g * 128 + col) = make_float2(acc[g][nt][2 * e], acc[g][nt][2 * e + 1]);
        }
    }
}

// ---------------- step 0 (h=0 -> gh = 0) ----------------
__global__ void k_step0(const int* __restrict__ src, const float* __restrict__ bih,
                        const float* __restrict__ bhh) {
    int i = blockIdx.x * 2 + (threadIdx.x >> 7);
    int c = threadIdx.x & 127;
    if (i >= NN) return;
    float h = 0.f;
    if (i < g_act[0]) {
        int n = g_perm[i];
        int s = src[(size_t)n * MD];
        const float* gi = g_gi + (size_t)s * G3;
        float r = sigm(gi[c] + bih[c] + bhh[c]);
        float z = sigm(gi[c + 128] + bih[c + 128] + bhh[c + 128]);
        float nn2 = tanhf(gi[c + 256] + bih[c + 256] + r * bhh[c + 256]);
        h = (1.f - z) * nn2;
    }
    float hf, lf;
    u32 hb = bf_rn(h, hf);
    u32 lb = bf_rn(h - hf, lf);
    g_hs[(size_t)i * 256 + c] = (u16)hb;
    g_hs[(size_t)i * 256 + 128 + c] = (u16)lb;
}

// ---------------- fused gh-GEMM + GRU gate (per step t) ----------------
__global__ void __launch_bounds__(256) k_ghgate(const int* __restrict__ src,
                                                const float* __restrict__ bih,
                                                const float* __restrict__ bhh, int t) {
    int tile = blockIdx.x;
    int Aend = g_act[t];
    if (tile * 32 >= Aend) return;
    extern __shared__ char sm[];
    float* sbr  = (float*)(sm + SM_BIAS);
    float* sbz  = sbr + 128;
    float* sbni = sbz + 128;
    float* sbnh = sbni + 128;
    int tid = threadIdx.x, lane = tid & 31, wid = tid >> 5;
    int wm = wid >> 2, wn = wid & 3;
    if (tid < 128) {
        sbr[tid]  = bih[tid] + bhh[tid];
        sbz[tid]  = bih[128 + tid] + bhh[128 + tid];
        sbni[tid] = bih[256 + tid];
        sbnh[tid] = bhh[256 + tid];
    }
    ldA32(sm + SM_A, g_hs, tile * 32, tid);
    u32 As = su32(sm + SM_A), Bs = su32(sm + SM_B);
    float acc[3][4][4] = {};
#pragma unroll 1
    for (int g = 0; g < 3; ++g) {
        __syncthreads();
        ldB128(sm + SM_B, g_whh2 + (size_t)g * 128 * 256, tid);
        __syncthreads();
        gemm_pass(As, Bs, lane, wm, wn, acc[g]);
    }
    int qr = lane >> 2, qc = (lane & 3) * 2;
#pragma unroll
    for (int e = 0; e < 2; ++e) {
        int R = tile * 32 + wm * 16 + qr + 8 * e;
        if (R < Aend) {
            int n = g_perm[R];
            int s = src[(size_t)n * MD + t];
            const float* gi = g_gi + (size_t)s * G3;
            u32* h32 = (u32*)(g_hs + (size_t)R * 256);
#pragma unroll
            for (int nt = 0; nt < 4; ++nt) {
                int col = wn * 32 + nt * 8 + qc;
                float2 gr = *(const float2*)(gi + col);
                float2 gz = *(const float2*)(gi + 128 + col);
                float2 gn = *(const float2*)(gi + 256 + col);
                u32 hp = h32[col >> 1], lp = h32[64 + (col >> 1)];
                float hprev0 = bf2f_lo(hp) + bf2f_lo(lp);
                float hprev1 = bf2f_hi(hp) + bf2f_hi(lp);
                float r0 = sigm(gr.x + acc[0][nt][2 * e]     + sbr[col]);
                float r1 = sigm(gr.y + acc[0][nt][2 * e + 1] + sbr[col + 1]);
                float z0 = sigm(gz.x + acc[1][nt][2 * e]     + sbz[col]);
                float z1 = sigm(gz.y + acc[1][nt][2 * e + 1] + sbz[col + 1]);
                float n0 = tanhf(gn.x + sbni[col]     + r0 * (acc[2][nt][2 * e]     + sbnh[col]));
                float n1 = tanhf(gn.y + sbni[col + 1] + r1 * (acc[2][nt][2 * e + 1] + sbnh[col + 1]));
                float hn0 = (1.f - z0) * n0 + z0 * hprev0;
                float hn1 = (1.f - z1) * n1 + z1 * hprev1;
                float f0, f1;
                u32 a0 = bf_rn(hn0, f0), a1 = bf_rn(hn1, f1);
                u32 b0 = bf_rn(hn0 - f0, f0), b1 = bf_rn(hn1 - f1, f1);
                h32[col >> 1]        = a0 | (a1 << 16);
                h32[64 + (col >> 1)] = b0 | (b1 << 16);
            }
        }
    }
}

// ---------------- final: out[perm[i]] = x[perm[i]]@Wself^T + h[i]@Wneigh^T ----------------
__global__ void __launch_bounds__(256) k_final_mm(float* __restrict__ out) {
    extern __shared__ char sm[];
    int tid = threadIdx.x, lane = tid & 31, wid = tid >> 5;
    int wm = wid >> 2, wn = wid & 3;
    int tile = blockIdx.x;
    u32 As = su32(sm + SM_A), Bs = su32(sm + SM_B);
    float acc[4][4] = {};

    ldA32_g(sm + SM_A, g_xs, g_perm, tile * 32, tid);
    ldB128(sm + SM_B, g_wself2, tid);
    __syncthreads();
    gemm_pass(As, Bs, lane, wm, wn, acc);
    __syncthreads();

    ldA32(sm + SM_A, g_hs, tile * 32, tid);
    ldB128(sm + SM_B, g_wneigh2, tid);
    __syncthreads();
    gemm_pass(As, Bs, lane, wm, wn, acc);

    int qr = lane >> 2, qc = (lane & 3) * 2;
#pragma unroll
    for (int e = 0; e < 2; ++e) {
        int R = tile * 32 + wm * 16 + qr + 8 * e;
        int n = g_perm[R];
        float* dst = out + (size_t)n * DD;
#pragma unroll
        for (int nt = 0; nt < 4; ++nt) {
            int col = wn * 32 + nt * 8 + qc;
            *(float2*)(dst + col) = make_float2(acc[nt][2 * e], acc[nt][2 * e + 1]);
        }
    }
}

// ---------------- launch ----------------
extern "C" void kernel_launch(void* const* d_in, const int* in_sizes, int n_in,
                              void* d_out, int out_size) {
    const float* feat    = (const float*)d_in[0];
    const float* gamma   = (const float*)d_in[1];
    const float* beta    = (const float*)d_in[2];
    const float* W_ih    = (const float*)d_in[3];
    const float* W_hh    = (const float*)d_in[4];
    const float* b_ih    = (const float*)d_in[5];
    const float* b_hh    = (const float*)d_in[6];
    const float* W_self  = (const float*)d_in[7];
    const float* W_neigh = (const float*)d_in[8];
    const int*   src     = (const int*)d_in[9];
    const void*  mask    = (const void*)d_in[10];
    float* out = (float*)d_out;

    cudaFuncSetAttribute(k_gi_mm,    cudaFuncAttributeMaxDynamicSharedMemorySize, SMT);
    cudaFuncSetAttribute(k_ghgate,   cudaFuncAttributeMaxDynamicSharedMemorySize, SMT);
    cudaFuncSetAttribute(k_final_mm, cudaFuncAttributeMaxDynamicSharedMemorySize, SMT);

    k_detect<<<1, 256>>>((const unsigned char*)mask);
    k_zero<<<1, 32>>>();
    k_stats<<<RB, 128>>>(feat);
    k_deg<<<RB, 256>>>(mask);
    k_finalize<<<1, 128>>>(gamma, beta);
    k_scatter<<<RB, 256>>>(mask);
    k_normsplit<<<(NN * DD / 4 + 255) / 256, 256>>>(feat);
    k_wsplit<<<128, 256>>>(W_ih, W_hh, W_self, W_neigh);
    k_gi_mm<<<NT32, 256, SMT>>>();
    k_step0<<<(NN + 1) / 2, 256>>>(src, b_ih, b_hh);
    for (int t = 1; t < MD; ++t)
        k_ghgate<<<NT32, 256, SMT>>>(src, b_ih, b_hh, t);
    k_final_mm<<<NT32, 256, SMT>>>(out);
}

// round 10
// speedup vs baseline: 2.6596x; 2.6596x over previous
#include <cuda_runtime.h>
#include <math.h>

typedef unsigned int u32;
typedef unsigned short u16;

#define NN 200000
#define MD 12
#define RB ((NN + 255) / 256)         // 782
#define NGRP (NN / 16)                // 12500 row-groups of 16
#define PGRID 148

#define WROW 528                      // padded smem row: 264 u16
#define SM_GI (384 * WROW + 1536)     // W_ih + folded biases
#define SM_SC (384 * WROW + 512 + 64) // W_hh + bhh_n + act
#define SM_FN (256 * WROW)            // W_self | W_neigh

// ---------------- scratch (device globals: allocation-free) ----------------
__device__ __align__(256) float g_gi[(size_t)NN * 384];   // x@W_ih^T + folded biases
__device__ __align__(256) u16 g_xs[(size_t)NN * 256];     // x split [hi128|lo128] bf16
__device__ __align__(256) u16 g_hs[(size_t)NN * 256];     // final h split (sorted order)
__device__ __align__(256) u16 g_wih2[384 * 256];
__device__ __align__(256) u16 g_whh2[384 * 256];
__device__ __align__(256) u16 g_wself2[128 * 256];
__device__ __align__(256) u16 g_wneigh2[128 * 256];
__device__ float g_psum[RB * 128];
__device__ float g_psq [RB * 128];
__device__ float g_a[128], g_b[128];
__device__ int   g_cnt[MD + 1], g_cur[MD + 1], g_act[MD];
__device__ int   g_perm[NN];
__device__ int   g_mtype;
__device__ u32   g_wctr[4];

__device__ __forceinline__ float sigm(float x) { return 1.0f / (1.0f + expf(-x)); }

__device__ __forceinline__ u32 bf_rn(float v, float& asf) {
    u32 u = __float_as_uint(v);
    u32 r = (u + 0x7FFFu + ((u >> 16) & 1u)) & 0xFFFF0000u;
    asf = __uint_as_float(r);
    return r >> 16;
}
__device__ __forceinline__ u32 pk(float hi, float lo) {
    u32 d; asm("cvt.rn.bf16x2.f32 %0, %1, %2;" : "=r"(d) : "f"(hi), "f"(lo)); return d;
}
__device__ __forceinline__ float lof(u32 a) { return __uint_as_float(a << 16); }
__device__ __forceinline__ float hif(u32 a) { return __uint_as_float(a & 0xFFFF0000u); }

__device__ __forceinline__ u32 su32(const void* p) {
    return (u32)__cvta_generic_to_shared(p);
}
__device__ __forceinline__ void ldsm4(u32& r0, u32& r1, u32& r2, u32& r3, u32 a) {
    asm volatile("ldmatrix.sync.aligned.m8n8.x4.shared.b16 {%0,%1,%2,%3}, [%4];"
                 : "=r"(r0), "=r"(r1), "=r"(r2), "=r"(r3) : "r"(a));
}
__device__ __forceinline__ void mma_bf16(float* c, u32 a0, u32 a1, u32 a2, u32 a3,
                                         u32 b0, u32 b1) {
    asm volatile("mma.sync.aligned.m16n8k16.row.col.f32.bf16.bf16.f32 "
                 "{%0,%1,%2,%3}, {%4,%5,%6,%7}, {%8,%9}, {%0,%1,%2,%3};"
                 : "+f"(c[0]), "+f"(c[1]), "+f"(c[2]), "+f"(c[3])
                 : "r"(a0), "r"(a1), "r"(a2), "r"(a3), "r"(b0), "r"(b1));
}

// GEMM inner: held A frags (hi+lo) x resident B gate (3 products) -> acc[16][4]
__device__ __forceinline__ void ga_gemm(const u32* ah, const u32* al, u32 BsG, int lane,
                                        float acc[16][4]) {
    u32 brow = BsG + (u32)(((((lane >> 4) << 3) + (lane & 7)) * WROW) + ((lane >> 3) & 1) * 16);
#pragma unroll
    for (int s = 0; s < 8; ++s) {
        u32 a0 = ah[4*s], a1 = ah[4*s+1], a2 = ah[4*s+2], a3 = ah[4*s+3];
        u32 l0 = al[4*s], l1 = al[4*s+1], l2 = al[4*s+2], l3 = al[4*s+3];
#pragma unroll
        for (int j2 = 0; j2 < 8; ++j2) {
            u32 base = brow + (u32)(j2 * 16 * WROW + 32 * s);
            u32 b0, b1, b2, b3, c0, c1, c2, c3;
            ldsm4(b0, b1, b2, b3, base);
            ldsm4(c0, c1, c2, c3, base + 256);
            mma_bf16(acc[2*j2],   a0, a1, a2, a3, b0, b1);
            mma_bf16(acc[2*j2+1], a0, a1, a2, a3, b2, b3);
            mma_bf16(acc[2*j2],   l0, l1, l2, l3, b0, b1);
            mma_bf16(acc[2*j2+1], l0, l1, l2, l3, b2, b3);
            mma_bf16(acc[2*j2],   a0, a1, a2, a3, c0, c1);
            mma_bf16(acc[2*j2+1], a0, a1, a2, a3, c2, c3);
        }
    }
}

// GEMM inner with A built on the fly from fp32 h registers
__device__ __forceinline__ void gh_gemm(const float h[16][4], u32 BsG, int lane,
                                        float acc[16][4]) {
    u32 brow = BsG + (u32)(((((lane >> 4) << 3) + (lane & 7)) * WROW) + ((lane >> 3) & 1) * 16);
#pragma unroll
    for (int s = 0; s < 8; ++s) {
        u32 a0 = pk(h[2*s][1],   h[2*s][0]);
        u32 a1 = pk(h[2*s][3],   h[2*s][2]);
        u32 a2 = pk(h[2*s+1][1], h[2*s+1][0]);
        u32 a3 = pk(h[2*s+1][3], h[2*s+1][2]);
        u32 l0 = pk(h[2*s][1]   - hif(a0), h[2*s][0]   - lof(a0));
        u32 l1 = pk(h[2*s][3]   - hif(a1), h[2*s][2]   - lof(a1));
        u32 l2 = pk(h[2*s+1][1] - hif(a2), h[2*s+1][0] - lof(a2));
        u32 l3 = pk(h[2*s+1][3] - hif(a3), h[2*s+1][2] - lof(a3));
#pragma unroll
        for (int j2 = 0; j2 < 8; ++j2) {
            u32 base = brow + (u32)(j2 * 16 * WROW + 32 * s);
            u32 b0, b1, b2, b3, c0, c1, c2, c3;
            ldsm4(b0, b1, b2, b3, base);
            ldsm4(c0, c1, c2, c3, base + 256);
            mma_bf16(acc[2*j2],   a0, a1, a2, a3, b0, b1);
            mma_bf16(acc[2*j2+1], a0, a1, a2, a3, b2, b3);
            mma_bf16(acc[2*j2],   l0, l1, l2, l3, b0, b1);
            mma_bf16(acc[2*j2+1], l0, l1, l2, l3, b2, b3);
            mma_bf16(acc[2*j2],   a0, a1, a2, a3, c0, c1);
            mma_bf16(acc[2*j2+1], a0, a1, a2, a3, c2, c3);
        }
    }
}

__device__ __forceinline__ void load_frags(const u16* rA, const u16* rB, int qc2,
                                           u32* ah, u32* al) {
#pragma unroll
    for (int s = 0; s < 8; ++s) {
        ah[4*s]   = *(const u32*)(rA + 16*s + qc2);
        ah[4*s+1] = *(const u32*)(rB + 16*s + qc2);
        ah[4*s+2] = *(const u32*)(rA + 16*s + 8 + qc2);
        ah[4*s+3] = *(const u32*)(rB + 16*s + 8 + qc2);
        al[4*s]   = *(const u32*)(rA + 128 + 16*s + qc2);
        al[4*s+1] = *(const u32*)(rB + 128 + 16*s + qc2);
        al[4*s+2] = *(const u32*)(rA + 128 + 16*s + 8 + qc2);
        al[4*s+3] = *(const u32*)(rB + 128 + 16*s + 8 + qc2);
    }
}

__device__ __forceinline__ void copy_w(char* sm, const u16* w, int rows, int tid) {
    for (int idx = tid; idx < rows * 32; idx += 256) {
        int r = idx >> 5, c = idx & 31;
        uint4 v = ((const uint4*)w)[idx];
        *(uint4*)(sm + r * WROW + c * 16) = v;
    }
}

// ---------------- mask dtype detection / setup (verified in R6/R8) ----------------
__global__ void k_detect(const unsigned char* __restrict__ m) {
    __shared__ int has3F, nzNot0, nz0;
    if (threadIdx.x == 0) { has3F = 0; nzNot0 = 0; nz0 = 0; }
    __syncthreads();
    for (int i = threadIdx.x; i < 16384; i += 256) {
        unsigned char b = m[i];
        if (b == 0x3F) atomicOr(&has3F, 1);
        if (b != 0 && (i & 3) != 0) atomicOr(&nzNot0, 1);
        if (b != 0 && (i & 3) == 0) atomicOr(&nz0, 1);
    }
    __syncthreads();
    if (threadIdx.x == 0) {
        int ty;
        if (has3F && nz0) ty = 3;
        else if (has3F)   ty = 2;
        else if (nzNot0)  ty = 0;
        else              ty = 1;
        g_mtype = ty;
    }
}

__device__ __forceinline__ int deg_any(const void* m, int n) {
    int ty = g_mtype;
    int d = 0;
    if (ty == 1) {
        const int* p = (const int*)m + (size_t)n * MD;
#pragma unroll
        for (int j = 0; j < MD; ++j) d += (p[j] != 0);
    } else if (ty == 0) {
        const unsigned char* p = (const unsigned char*)m + (size_t)n * MD;
#pragma unroll
        for (int j = 0; j < MD; ++j) d += (p[j] != 0);
    } else if (ty == 2) {
        const float* p = (const float*)m + (size_t)n * MD;
#pragma unroll
        for (int j = 0; j < MD; ++j) d += (p[j] != 0.0f);
    } else {
        const u16* p = (const u16*)m + (size_t)n * MD;
#pragma unroll
        for (int j = 0; j < MD; ++j) d += ((p[j] & 0x7FFF) != 0);
    }
    return d;
}

__global__ void k_zero() {
    int t = threadIdx.x;
    if (t <= MD) g_cnt[t] = 0;
    if (t < 4) g_wctr[t] = 0;
}

__global__ void k_stats(const float* __restrict__ feat) {
    int col = threadIdx.x;
    int r0 = blockIdx.x * 256;
    int rend = min(r0 + 256, NN);
    float s = 0.f, q = 0.f;
    for (int r = r0; r < rend; ++r) {
        float v = feat[(size_t)r * 128 + col];
        s += v; q += v * v;
    }
    g_psum[blockIdx.x * 128 + col] = s;
    g_psq [blockIdx.x * 128 + col] = q;
}

__global__ void k_deg(const void* __restrict__ mask) {
    __shared__ int c[MD + 1];
    int tid = threadIdx.x;
    if (tid <= MD) c[tid] = 0;
    __syncthreads();
    int n = blockIdx.x * 256 + tid;
    if (n < NN) atomicAdd(&c[deg_any(mask, n)], 1);
    __syncthreads();
    if (tid <= MD && c[tid] > 0) atomicAdd(&g_cnt[tid], c[tid]);
}

__global__ void k_finalize(const float* __restrict__ gamma, const float* __restrict__ beta) {
    int t = threadIdx.x;
    float s = 0.f, q = 0.f;
    for (int b = 0; b < RB; ++b) { s += g_psum[b * 128 + t]; q += g_psq[b * 128 + t]; }
    float mu = s * (1.0f / NN);
    float var = q * (1.0f / NN) - mu * mu;
    float rs = rsqrtf(var + 1e-5f);
    float a = rs * gamma[t];
    g_a[t] = a;
    g_b[t] = beta[t] - mu * a;
    if (t == 0) {
        int suf = 0;
        for (int d = MD; d >= 0; --d) { g_cur[d] = suf; suf += g_cnt[d]; }
        for (int sdx = 0; sdx < MD; ++sdx) g_act[sdx] = g_cur[sdx];
    }
}

__global__ void k_scatter(const void* __restrict__ mask) {
    int n = blockIdx.x * 256 + threadIdx.x;
    if (n >= NN) return;
    int pos = atomicAdd(&g_cur[deg_any(mask, n)], 1);
    g_perm[pos] = n;
}

__global__ void k_normsplit(const float* __restrict__ feat) {
    int i = blockIdx.x * 256 + threadIdx.x;
    if (i >= NN * 32) return;
    float4 v = ((const float4*)feat)[i];
    int row = i >> 5;
    int c = (i & 31) << 2;
    float f0 = v.x * g_a[c + 0] + g_b[c + 0];
    float f1 = v.y * g_a[c + 1] + g_b[c + 1];
    float f2 = v.z * g_a[c + 2] + g_b[c + 2];
    float f3 = v.w * g_a[c + 3] + g_b[c + 3];
    float h0, h1, h2, h3, d0;
    u32 a0 = bf_rn(f0, h0), a1 = bf_rn(f1, h1), a2 = bf_rn(f2, h2), a3 = bf_rn(f3, h3);
    u32 b0 = bf_rn(f0 - h0, d0), b1 = bf_rn(f1 - h1, d0), b2 = bf_rn(f2 - h2, d0), b3 = bf_rn(f3 - h3, d0);
    u16* dst = g_xs + (size_t)row * 256;
    *(uint2*)(dst + c)       = make_uint2(a0 | (a1 << 16), a2 | (a3 << 16));
    *(uint2*)(dst + 128 + c) = make_uint2(b0 | (b1 << 16), b2 | (b3 << 16));
}

__global__ void k_wsplit(const float* __restrict__ wih, const float* __restrict__ whh,
                         const float* __restrict__ wself, const float* __restrict__ wneigh) {
    int i = blockIdx.x * 256 + threadIdx.x;
    int row = i >> 5;
    int c = (i & 31) << 2;
    const float* src;
    u16* dst;
    if (row < 384)      { src = wih + (size_t)row * 128;            dst = g_wih2 + (size_t)row * 256; }
    else if (row < 768) { src = whh + (size_t)(row - 384) * 128;    dst = g_whh2 + (size_t)(row - 384) * 256; }
    else if (row < 896) { src = wself + (size_t)(row - 768) * 128;  dst = g_wself2 + (size_t)(row - 768) * 256; }
    else                { src = wneigh + (size_t)(row - 896) * 128; dst = g_wneigh2 + (size_t)(row - 896) * 256; }
    float4 v = *(const float4*)(src + c);
    float h0, h1, h2, h3, dm;
    u32 a0 = bf_rn(v.x, h0), a1 = bf_rn(v.y, h1), a2 = bf_rn(v.z, h2), a3 = bf_rn(v.w, h3);
    u32 b0 = bf_rn(v.x - h0, dm), b1 = bf_rn(v.y - h1, dm), b2 = bf_rn(v.z - h2, dm), b3 = bf_rn(v.w - h3, dm);
    *(uint2*)(dst + c)       = make_uint2(a0 | (a1 << 16), a2 | (a3 << 16));
    *(uint2*)(dst + 128 + c) = make_uint2(b0 | (b1 << 16), b2 | (b3 << 16));
}

// ---------------- persistent gi GEMM: g_gi = x @ W_ih^T + folded biases ----------------
__global__ void __launch_bounds__(256, 1) k_gi_p(const float* __restrict__ bih,
                                                 const float* __restrict__ bhh) {
    extern __shared__ char sm[];
    int tid = threadIdx.x, lane = tid & 31;
    copy_w(sm, g_wih2, 384, tid);
    float* sb = (float*)(sm + 384 * WROW);
    for (int j = tid; j < 384; j += 256)
        sb[j] = bih[j] + (j < 256 ? bhh[j] : 0.f);
    __syncthreads();
    u32 Bs = su32(sm);
    int qr = lane >> 2, qc2 = (lane & 3) * 2;
    while (true) {
        u32 gid;
        if (lane == 0) gid = atomicAdd(&g_wctr[0], 1);
        gid = __shfl_sync(0xFFFFFFFFu, gid, 0);
        if (gid >= NGRP) break;
        int iA = gid * 16 + qr, iB = iA + 8;
        const u16* rA = g_xs + (size_t)iA * 256;
        const u16* rB = g_xs + (size_t)iB * 256;
        u32 ah[32], al[32];
        load_frags(rA, rB, qc2, ah, al);
        float* oA = g_gi + (size_t)iA * 384;
        float* oB = g_gi + (size_t)iB * 384;
#pragma unroll 1
        for (int g = 0; g < 3; ++g) {
            float acc[16][4];
#pragma unroll
            for (int j = 0; j < 16; ++j) { acc[j][0] = acc[j][1] = acc[j][2] = acc[j][3] = 0.f; }
            ga_gemm(ah, al, Bs + (u32)(g * 128 * WROW), lane, acc);
#pragma unroll
            for (int j = 0; j < 16; ++j) {
                int col = g * 128 + 8 * j + qc2;
                float b0 = sb[col], b1 = sb[col + 1];
                *(float2*)(oA + col) = make_float2(acc[j][0] + b0, acc[j][1] + b1);
                *(float2*)(oB + col) = make_float2(acc[j][2] + b0, acc[j][3] + b1);
            }
        }
    }
}

// ---------------- persistent 12-step GRU scan (h in registers) ----------------
__global__ void __launch_bounds__(256, 1) k_scan_p(const int* __restrict__ src,
                                                   const float* __restrict__ bhh) {
    extern __shared__ char sm[];
    int tid = threadIdx.x, lane = tid & 31;
    copy_w(sm, g_whh2, 384, tid);
    float* sbn = (float*)(sm + 384 * WROW);
    int* sact = (int*)(sbn + 128);
    if (tid < 128) sbn[tid] = bhh[256 + tid];
    if (tid < MD) sact[tid] = g_act[tid];
    __syncthreads();
    u32 Bs = su32(sm);
    int qr = lane >> 2, qc2 = (lane & 3) * 2;
    while (true) {
        u32 gid;
        if (lane == 0) gid = atomicAdd(&g_wctr[1], 1);
        gid = __shfl_sync(0xFFFFFFFFu, gid, 0);
        if (gid >= NGRP) break;
        int i0 = (int)gid * 16;
        int iA = i0 + qr, iB = iA + 8;
        int nA = g_perm[iA], nB = g_perm[iB];
        const int* sAp = src + (size_t)nA * MD;
        const int* sBp = src + (size_t)nB * MD;
        float h[16][4];
#pragma unroll
        for (int j = 0; j < 16; ++j) { h[j][0] = h[j][1] = h[j][2] = h[j][3] = 0.f; }
#pragma unroll 1
        for (int t = 0; t < MD; ++t) {
            int actT = sact[t];
            if (actT <= i0) break;
            bool aA = iA < actT, aB = iB < actT;
            int sA = __ldg(sAp + t), sB = __ldg(sBp + t);
            const float* giA = g_gi + (size_t)sA * 384;
            const float* giB = g_gi + (size_t)sB * 384;
            float accA[16][4], accB[16][4];
#pragma unroll
            for (int j = 0; j < 16; ++j) { accA[j][0] = accA[j][1] = accA[j][2] = accA[j][3] = 0.f; }
            if (t) gh_gemm(h, Bs, lane, accA);                       // gh_r
#pragma unroll
            for (int j = 0; j < 16; ++j) {                           // r (in place)
                int col = 8 * j + qc2;
                float2 gA = *(const float2*)(giA + col);
                float2 gB = *(const float2*)(giB + col);
                accA[j][0] = sigm(accA[j][0] + gA.x);
                accA[j][1] = sigm(accA[j][1] + gA.y);
                accA[j][2] = sigm(accA[j][2] + gB.x);
                accA[j][3] = sigm(accA[j][3] + gB.y);
            }
#pragma unroll
            for (int j = 0; j < 16; ++j) { accB[j][0] = accB[j][1] = accB[j][2] = accB[j][3] = 0.f; }
            if (t) gh_gemm(h, Bs + (u32)(256 * WROW), lane, accB);   // gh_n
#pragma unroll
            for (int j = 0; j < 16; ++j) {                           // n (in place in accB)
                int col = 8 * j + qc2;
                float2 gA = *(const float2*)(giA + 256 + col);
                float2 gB = *(const float2*)(giB + 256 + col);
                float b0 = sbn[col], b1 = sbn[col + 1];
                accB[j][0] = tanhf(gA.x + accA[j][0] * (accB[j][0] + b0));
                accB[j][1] = tanhf(gA.y + accA[j][1] * (accB[j][1] + b1));
                accB[j][2] = tanhf(gB.x + accA[j][2] * (accB[j][2] + b0));
                accB[j][3] = tanhf(gB.y + accA[j][3] * (accB[j][3] + b1));
            }
#pragma unroll
            for (int j = 0; j < 16; ++j) { accA[j][0] = accA[j][1] = accA[j][2] = accA[j][3] = 0.f; }
            if (t) gh_gemm(h, Bs + (u32)(128 * WROW), lane, accA);   // gh_z
#pragma unroll
            for (int j = 0; j < 16; ++j) {                           // z + h update
                int col = 8 * j + qc2;
                float2 gA = *(const float2*)(giA + 128 + col);
                float2 gB = *(const float2*)(giB + 128 + col);
                float z0 = sigm(accA[j][0] + gA.x);
                float z1 = sigm(accA[j][1] + gA.y);
                float z2 = sigm(accA[j][2] + gB.x);
                float z3 = sigm(accA[j][3] + gB.y);
                if (aA) {
                    h[j][0] = (1.f - z0) * accB[j][0] + z0 * h[j][0];
                    h[j][1] = (1.f - z1) * accB[j][1] + z1 * h[j][1];
                }
                if (aB) {
                    h[j][2] = (1.f - z2) * accB[j][2] + z2 * h[j][2];
                    h[j][3] = (1.f - z3) * accB[j][3] + z3 * h[j][3];
                }
            }
        }
        u16* hA = g_hs + (size_t)iA * 256;
        u16* hB = g_hs + (size_t)iB * 256;
#pragma unroll
        for (int j = 0; j < 16; ++j) {
            int col = 8 * j + qc2;
            u32 w0 = pk(h[j][1], h[j][0]);
            u32 l0 = pk(h[j][1] - hif(w0), h[j][0] - lof(w0));
            u32 w1 = pk(h[j][3], h[j][2]);
            u32 l1 = pk(h[j][3] - hif(w1), h[j][2] - lof(w1));
            *(u32*)(hA + col) = w0;  *(u32*)(hA + 128 + col) = l0;
            *(u32*)(hB + col) = w1;  *(u32*)(hB + 128 + col) = l1;
        }
    }
}

// ---------------- persistent final GEMM ----------------
__global__ void __launch_bounds__(256, 1) k_final_p(float* __restrict__ out) {
    extern __shared__ char sm[];
    int tid = threadIdx.x, lane = tid & 31;
    copy_w(sm, g_wself2, 128, tid);
    copy_w(sm + 128 * WROW, g_wneigh2, 128, tid);
    __syncthreads();
    u32 Bs = su32(sm);
    int qr = lane >> 2, qc2 = (lane & 3) * 2;
    while (true) {
        u32 gid;
        if (lane == 0) gid = atomicAdd(&g_wctr[2], 1);
        gid = __shfl_sync(0xFFFFFFFFu, gid, 0);
        if (gid >= NGRP) break;
        int iA = (int)gid * 16 + qr, iB = iA + 8;
        int nA = g_perm[iA], nB = g_perm[iB];
        float acc[16][4];
#pragma unroll
        for (int j = 0; j < 16; ++j) { acc[j][0] = acc[j][1] = acc[j][2] = acc[j][3] = 0.f; }
        {
            u32 ah[32], al[32];
            load_frags(g_xs + (size_t)nA * 256, g_xs + (size_t)nB * 256, qc2, ah, al);
            ga_gemm(ah, al, Bs, lane, acc);
        }
        {
            u32 ah[32], al[32];
            load_frags(g_hs + (size_t)iA * 256, g_hs + (size_t)iB * 256, qc2, ah, al);
            ga_gemm(ah, al, Bs + (u32)(128 * WROW), lane, acc);
        }
        float* oA = out + (size_t)nA * 128;
        float* oB = out + (size_t)nB * 128;
#pragma unroll
        for (int j = 0; j < 16; ++j) {
            int col = 8 * j + qc2;
            *(float2*)(oA + col) = make_float2(acc[j][0], acc[j][1]);
            *(float2*)(oB + col) = make_float2(acc[j][2], acc[j][3]);
        }
    }
}

// ---------------- launch ----------------
extern "C" void kernel_launch(void* const* d_in, const int* in_sizes, int n_in,
                              void* d_out, int out_size) {
    const float* feat    = (const float*)d_in[0];
    const float* gamma   = (const float*)d_in[1];
    const float* beta    = (const float*)d_in[2];
    const float* W_ih    = (const float*)d_in[3];
    const float* W_hh    = (const float*)d_in[4];
    const float* b_ih    = (const float*)d_in[5];
    const float* b_hh    = (const float*)d_in[6];
    const float* W_self  = (const float*)d_in[7];
    const float* W_neigh = (const float*)d_in[8];
    const int*   src     = (const int*)d_in[9];
    const void*  mask    = (const void*)d_in[10];
    float* out = (float*)d_out;

    cudaFuncSetAttribute(k_gi_p,    cudaFuncAttributeMaxDynamicSharedMemorySize, SM_GI);
    cudaFuncSetAttribute(k_scan_p,  cudaFuncAttributeMaxDynamicSharedMemorySize, SM_SC);
    cudaFuncSetAttribute(k_final_p, cudaFuncAttributeMaxDynamicSharedMemorySize, SM_FN);

    k_detect<<<1, 256>>>((const unsigned char*)mask);
    k_zero<<<1, 32>>>();
    k_stats<<<RB, 128>>>(feat);
    k_deg<<<RB, 256>>>(mask);
    k_finalize<<<1, 128>>>(gamma, beta);
    k_scatter<<<RB, 256>>>(mask);
    k_normsplit<<<(NN * 32 + 255) / 256, 256>>>(feat);
    k_wsplit<<<128, 256>>>(W_ih, W_hh, W_self, W_neigh);
    k_gi_p<<<PGRID, 256, SM_GI>>>(b_ih, b_hh);
    k_scan_p<<<PGRID, 256, SM_SC>>>(src, b_hh);
    k_final_p<<<PGRID, 256, SM_FN>>>(out);
}

// round 11
// speedup vs baseline: 3.4639x; 1.3024x over previous
#include <cuda_runtime.h>
#include <math.h>

typedef unsigned int u32;
typedef unsigned short u16;

#define NN 200000
#define MD 12
#define RB ((NN + 255) / 256)         // 782
#define NGRP (NN / 16)                // 12500 row-groups of 16
#define PGRID 148

#define WROW 528                      // padded smem row: 264 u16
#define SM_GI (384 * WROW + 1536)     // W_ih + folded biases
#define SM_SC (384 * WROW + 512 + 64) // W_hh + bhh_n + act
#define SM_FN (256 * WROW)            // W_self | W_neigh

// ---------------- scratch (device globals: allocation-free) ----------------
__device__ __align__(256) float g_gi[(size_t)NN * 384];   // x@W_ih^T + folded biases
__device__ __align__(256) u16 g_xs[(size_t)NN * 256];     // x split [hi128|lo128] bf16
__device__ __align__(256) u16 g_hs[(size_t)NN * 256];     // final h split (sorted order)
__device__ __align__(256) u16 g_wih2[384 * 256];
__device__ __align__(256) u16 g_whh2[384 * 256];
__device__ __align__(256) u16 g_wself2[128 * 256];
__device__ __align__(256) u16 g_wneigh2[128 * 256];
__device__ float g_psum[RB * 128];
__device__ float g_psq [RB * 128];
__device__ float g_a[128], g_b[128];
__device__ int   g_cnt[MD + 1], g_cur[MD + 1], g_act[MD];
__device__ int   g_perm[NN];
__device__ int   g_mtype;
__device__ u32   g_wctr[4];

__device__ __forceinline__ float sigm(float x) { return 1.0f / (1.0f + expf(-x)); }
// fast activations (approx MUFU paths): ~1e-6 added error
__device__ __forceinline__ float sigm_f(float x) {
    return __fdividef(1.0f, 1.0f + __expf(-x));
}
__device__ __forceinline__ float tanh_f(float x) {
    return 1.0f - __fdividef(2.0f, __expf(2.0f * x) + 1.0f);
}

__device__ __forceinline__ u32 bf_rn(float v, float& asf) {
    u32 u = __float_as_uint(v);
    u32 r = (u + 0x7FFFu + ((u >> 16) & 1u)) & 0xFFFF0000u;
    asf = __uint_as_float(r);
    return r >> 16;
}
__device__ __forceinline__ u32 pk(float hi, float lo) {
    u32 d; asm("cvt.rn.bf16x2.f32 %0, %1, %2;" : "=r"(d) : "f"(hi), "f"(lo)); return d;
}
__device__ __forceinline__ float lof(u32 a) { return __uint_as_float(a << 16); }
__device__ __forceinline__ float hif(u32 a) { return __uint_as_float(a & 0xFFFF0000u); }

__device__ __forceinline__ u32 su32(const void* p) {
    return (u32)__cvta_generic_to_shared(p);
}
__device__ __forceinline__ void ldsm4(u32& r0, u32& r1, u32& r2, u32& r3, u32 a) {
    asm volatile("ldmatrix.sync.aligned.m8n8.x4.shared.b16 {%0,%1,%2,%3}, [%4];"
                 : "=r"(r0), "=r"(r1), "=r"(r2), "=r"(r3) : "r"(a));
}
__device__ __forceinline__ void mma_bf16(float* c, u32 a0, u32 a1, u32 a2, u32 a3,
                                         u32 b0, u32 b1) {
    asm volatile("mma.sync.aligned.m16n8k16.row.col.f32.bf16.bf16.f32 "
                 "{%0,%1,%2,%3}, {%4,%5,%6,%7}, {%8,%9}, {%0,%1,%2,%3};"
                 : "+f"(c[0]), "+f"(c[1]), "+f"(c[2]), "+f"(c[3])
                 : "r"(a0), "r"(a1), "r"(a2), "r"(a3), "r"(b0), "r"(b1));
}

// GEMM inner: held A frags (hi+lo) x resident B gate (3 products) -> acc[16][4]
__device__ __forceinline__ void ga_gemm(const u32* ah, const u32* al, u32 BsG, int lane,
                                        float acc[16][4]) {
    u32 brow = BsG + (u32)(((((lane >> 4) << 3) + (lane & 7)) * WROW) + ((lane >> 3) & 1) * 16);
#pragma unroll
    for (int s = 0; s < 8; ++s) {
        u32 a0 = ah[4*s], a1 = ah[4*s+1], a2 = ah[4*s+2], a3 = ah[4*s+3];
        u32 l0 = al[4*s], l1 = al[4*s+1], l2 = al[4*s+2], l3 = al[4*s+3];
#pragma unroll
        for (int j2 = 0; j2 < 8; ++j2) {
            u32 base = brow + (u32)(j2 * 16 * WROW + 32 * s);
            u32 b0, b1, b2, b3, c0, c1, c2, c3;
            ldsm4(b0, b1, b2, b3, base);
            ldsm4(c0, c1, c2, c3, base + 256);
            mma_bf16(acc[2*j2],   a0, a1, a2, a3, b0, b1);
            mma_bf16(acc[2*j2+1], a0, a1, a2, a3, b2, b3);
            mma_bf16(acc[2*j2],   l0, l1, l2, l3, b0, b1);
            mma_bf16(acc[2*j2+1], l0, l1, l2, l3, b2, b3);
            mma_bf16(acc[2*j2],   a0, a1, a2, a3, c0, c1);
            mma_bf16(acc[2*j2+1], a0, a1, a2, a3, c2, c3);
        }
    }
}

__device__ __forceinline__ void load_frags(const u16* rA, const u16* rB, int qc2,
                                           u32* ah, u32* al) {
#pragma unroll
    for (int s = 0; s < 8; ++s) {
        ah[4*s]   = *(const u32*)(rA + 16*s + qc2);
        ah[4*s+1] = *(const u32*)(rB + 16*s + qc2);
        ah[4*s+2] = *(const u32*)(rA + 16*s + 8 + qc2);
        ah[4*s+3] = *(const u32*)(rB + 16*s + 8 + qc2);
        al[4*s]   = *(const u32*)(rA + 128 + 16*s + qc2);
        al[4*s+1] = *(const u32*)(rB + 128 + 16*s + qc2);
        al[4*s+2] = *(const u32*)(rA + 128 + 16*s + 8 + qc2);
        al[4*s+3] = *(const u32*)(rB + 128 + 16*s + 8 + qc2);
    }
}

__device__ __forceinline__ void copy_w(char* sm, const u16* w, int rows, int tid) {
    for (int idx = tid; idx < rows * 32; idx += 256) {
        int r = idx >> 5, c = idx & 31;
        uint4 v = ((const uint4*)w)[idx];
        *(uint4*)(sm + r * WROW + c * 16) = v;
    }
}

// ---------------- mask dtype detection / setup (verified in R6/R8/R10) ----------------
__global__ void k_detect(const unsigned char* __restrict__ m) {
    __shared__ int has3F, nzNot0, nz0;
    if (threadIdx.x == 0) { has3F = 0; nzNot0 = 0; nz0 = 0; }
    __syncthreads();
    for (int i = threadIdx.x; i < 16384; i += 256) {
        unsigned char b = m[i];
        if (b == 0x3F) atomicOr(&has3F, 1);
        if (b != 0 && (i & 3) != 0) atomicOr(&nzNot0, 1);
        if (b != 0 && (i & 3) == 0) atomicOr(&nz0, 1);
    }
    __syncthreads();
    if (threadIdx.x == 0) {
        int ty;
        if (has3F && nz0) ty = 3;
        else if (has3F)   ty = 2;
        else if (nzNot0)  ty = 0;
        else              ty = 1;
        g_mtype = ty;
    }
}

__device__ __forceinline__ int deg_any(const void* m, int n) {
    int ty = g_mtype;
    int d = 0;
    if (ty == 1) {
        const int* p = (const int*)m + (size_t)n * MD;
#pragma unroll
        for (int j = 0; j < MD; ++j) d += (p[j] != 0);
    } else if (ty == 0) {
        const unsigned char* p = (const unsigned char*)m + (size_t)n * MD;
#pragma unroll
        for (int j = 0; j < MD; ++j) d += (p[j] != 0);
    } else if (ty == 2) {
        const float* p = (const float*)m + (size_t)n * MD;
#pragma unroll
        for (int j = 0; j < MD; ++j) d += (p[j] != 0.0f);
    } else {
        const u16* p = (const u16*)m + (size_t)n * MD;
#pragma unroll
        for (int j = 0; j < MD; ++j) d += ((p[j] & 0x7FFF) != 0);
    }
    return d;
}

__global__ void k_zero() {
    int t = threadIdx.x;
    if (t <= MD) g_cnt[t] = 0;
    if (t < 4) g_wctr[t] = 0;
}

__global__ void k_stats(const float* __restrict__ feat) {
    int col = threadIdx.x;
    int r0 = blockIdx.x * 256;
    int rend = min(r0 + 256, NN);
    float s = 0.f, q = 0.f;
    for (int r = r0; r < rend; ++r) {
        float v = feat[(size_t)r * 128 + col];
        s += v; q += v * v;
    }
    g_psum[blockIdx.x * 128 + col] = s;
    g_psq [blockIdx.x * 128 + col] = q;
}

__global__ void k_deg(const void* __restrict__ mask) {
    __shared__ int c[MD + 1];
    int tid = threadIdx.x;
    if (tid <= MD) c[tid] = 0;
    __syncthreads();
    int n = blockIdx.x * 256 + tid;
    if (n < NN) atomicAdd(&c[deg_any(mask, n)], 1);
    __syncthreads();
    if (tid <= MD && c[tid] > 0) atomicAdd(&g_cnt[tid], c[tid]);
}

__global__ void k_finalize(const float* __restrict__ gamma, const float* __restrict__ beta) {
    int t = threadIdx.x;
    float s = 0.f, q = 0.f;
    for (int b = 0; b < RB; ++b) { s += g_psum[b * 128 + t]; q += g_psq[b * 128 + t]; }
    float mu = s * (1.0f / NN);
    float var = q * (1.0f / NN) - mu * mu;
    float rs = rsqrtf(var + 1e-5f);
    float a = rs * gamma[t];
    g_a[t] = a;
    g_b[t] = beta[t] - mu * a;
    if (t == 0) {
        int suf = 0;
        for (int d = MD; d >= 0; --d) { g_cur[d] = suf; suf += g_cnt[d]; }
        for (int sdx = 0; sdx < MD; ++sdx) g_act[sdx] = g_cur[sdx];
    }
}

__global__ void k_scatter(const void* __restrict__ mask) {
    int n = blockIdx.x * 256 + threadIdx.x;
    if (n >= NN) return;
    int pos = atomicAdd(&g_cur[deg_any(mask, n)], 1);
    g_perm[pos] = n;
}

__global__ void k_normsplit(const float* __restrict__ feat) {
    int i = blockIdx.x * 256 + threadIdx.x;
    if (i >= NN * 32) return;
    float4 v = ((const float4*)feat)[i];
    int row = i >> 5;
    int c = (i & 31) << 2;
    float f0 = v.x * g_a[c + 0] + g_b[c + 0];
    float f1 = v.y * g_a[c + 1] + g_b[c + 1];
    float f2 = v.z * g_a[c + 2] + g_b[c + 2];
    float f3 = v.w * g_a[c + 3] + g_b[c + 3];
    float h0, h1, h2, h3, d0;
    u32 a0 = bf_rn(f0, h0), a1 = bf_rn(f1, h1), a2 = bf_rn(f2, h2), a3 = bf_rn(f3, h3);
    u32 b0 = bf_rn(f0 - h0, d0), b1 = bf_rn(f1 - h1, d0), b2 = bf_rn(f2 - h2, d0), b3 = bf_rn(f3 - h3, d0);
    u16* dst = g_xs + (size_t)row * 256;
    *(uint2*)(dst + c)       = make_uint2(a0 | (a1 << 16), a2 | (a3 << 16));
    *(uint2*)(dst + 128 + c) = make_uint2(b0 | (b1 << 16), b2 | (b3 << 16));
}

__global__ void k_wsplit(const float* __restrict__ wih, const float* __restrict__ whh,
                         const float* __restrict__ wself, const float* __restrict__ wneigh) {
    int i = blockIdx.x * 256 + threadIdx.x;
    int row = i >> 5;
    int c = (i & 31) << 2;
    const float* src;
    u16* dst;
    if (row < 384)      { src = wih + (size_t)row * 128;            dst = g_wih2 + (size_t)row * 256; }
    else if (row < 768) { src = whh + (size_t)(row - 384) * 128;    dst = g_whh2 + (size_t)(row - 384) * 256; }
    else if (row < 896) { src = wself + (size_t)(row - 768) * 128;  dst = g_wself2 + (size_t)(row - 768) * 256; }
    else                { src = wneigh + (size_t)(row - 896) * 128; dst = g_wneigh2 + (size_t)(row - 896) * 256; }
    float4 v = *(const float4*)(src + c);
    float h0, h1, h2, h3, dm;
    u32 a0 = bf_rn(v.x, h0), a1 = bf_rn(v.y, h1), a2 = bf_rn(v.z, h2), a3 = bf_rn(v.w, h3);
    u32 b0 = bf_rn(v.x - h0, dm), b1 = bf_rn(v.y - h1, dm), b2 = bf_rn(v.z - h2, dm), b3 = bf_rn(v.w - h3, dm);
    *(uint2*)(dst + c)       = make_uint2(a0 | (a1 << 16), a2 | (a3 << 16));
    *(uint2*)(dst + 128 + c) = make_uint2(b0 | (b1 << 16), b2 | (b3 << 16));
}

// ---------------- persistent gi GEMM: g_gi = x @ W_ih^T + folded biases ----------------
__global__ void __launch_bounds__(256, 1) k_gi_p(const float* __restrict__ bih,
                                                 const float* __restrict__ bhh) {
    extern __shared__ char sm[];
    int tid = threadIdx.x, lane = tid & 31;
    copy_w(sm, g_wih2, 384, tid);
    float* sb = (float*)(sm + 384 * WROW);
    for (int j = tid; j < 384; j += 256)
        sb[j] = bih[j] + (j < 256 ? bhh[j] : 0.f);
    __syncthreads();
    u32 Bs = su32(sm);
    int qr = lane >> 2, qc2 = (lane & 3) * 2;
    while (true) {
        u32 gid;
        if (lane == 0) gid = atomicAdd(&g_wctr[0], 1);
        gid = __shfl_sync(0xFFFFFFFFu, gid, 0);
        if (gid >= NGRP) break;
        int iA = gid * 16 + qr, iB = iA + 8;
        const u16* rA = g_xs + (size_t)iA * 256;
        const u16* rB = g_xs + (size_t)iB * 256;
        u32 ah[32], al[32];
        load_frags(rA, rB, qc2, ah, al);
        float* oA = g_gi + (size_t)iA * 384;
        float* oB = g_gi + (size_t)iB * 384;
#pragma unroll 1
        for (int g = 0; g < 3; ++g) {
            float acc[16][4];
#pragma unroll
            for (int j = 0; j < 16; ++j) { acc[j][0] = acc[j][1] = acc[j][2] = acc[j][3] = 0.f; }
            ga_gemm(ah, al, Bs + (u32)(g * 128 * WROW), lane, acc);
#pragma unroll
            for (int j = 0; j < 16; ++j) {
                int col = g * 128 + 8 * j + qc2;
                float b0 = sb[col], b1 = sb[col + 1];
                *(float2*)(oA + col) = make_float2(acc[j][0] + b0, acc[j][1] + b1);
                *(float2*)(oB + col) = make_float2(acc[j][2] + b0, acc[j][3] + b1);
            }
        }
    }
}

// ---------------- persistent 12-step GRU scan (h kept as split-bf16 A-fragments) ----------------
__global__ void __launch_bounds__(256, 1) k_scan_p(const int* __restrict__ src,
                                                   const float* __restrict__ bhh) {
    extern __shared__ char sm[];
    int tid = threadIdx.x, lane = tid & 31;
    copy_w(sm, g_whh2, 384, tid);
    float* sbn = (float*)(sm + 384 * WROW);
    int* sact = (int*)(sbn + 128);
    if (tid < 128) sbn[tid] = bhh[256 + tid];
    if (tid < MD) sact[tid] = g_act[tid];
    __syncthreads();
    u32 Bs = su32(sm);
    int qr = lane >> 2, qc2 = (lane & 3) * 2;
    while (true) {
        u32 gid;
        if (lane == 0) gid = atomicAdd(&g_wctr[1], 1);
        gid = __shfl_sync(0xFFFFFFFFu, gid, 0);
        if (gid >= NGRP) break;
        int i0 = (int)gid * 16;
        int iA = i0 + qr, iB = iA + 8;
        int nA = g_perm[iA], nB = g_perm[iB];
        const int* sAp = src + (size_t)nA * MD;
        const int* sBp = src + (size_t)nB * MD;
        u32 ah[32], al[32];                 // h state as split-bf16 mma A-fragments
#pragma unroll
        for (int k = 0; k < 32; ++k) { ah[k] = 0u; al[k] = 0u; }
#pragma unroll 1
        for (int t = 0; t < MD; ++t) {
            int actT = sact[t];
            if (actT <= i0) break;
            bool aA = iA < actT, aB = iB < actT;
            int sA = __ldg(sAp + t), sB = __ldg(sBp + t);
            const float* giA = g_gi + (size_t)sA * 384;
            const float* giB = g_gi + (size_t)sB * 384;
            // ---- r gate ----
            float accR[16][4];
#pragma unroll
            for (int j = 0; j < 16; ++j) { accR[j][0] = accR[j][1] = accR[j][2] = accR[j][3] = 0.f; }
            if (t) ga_gemm(ah, al, Bs, lane, accR);
#pragma unroll
            for (int j = 0; j < 16; ++j) {
                int col = 8 * j + qc2;
                float2 gA = *(const float2*)(giA + col);
                float2 gB = *(const float2*)(giB + col);
                accR[j][0] = sigm_f(accR[j][0] + gA.x);
                accR[j][1] = sigm_f(accR[j][1] + gA.y);
                accR[j][2] = sigm_f(accR[j][2] + gB.x);
                accR[j][3] = sigm_f(accR[j][3] + gB.y);
            }
            // ---- n gate (r consumed here; accR freed after) ----
            float accN[16][4];
#pragma unroll
            for (int j = 0; j < 16; ++j) { accN[j][0] = accN[j][1] = accN[j][2] = accN[j][3] = 0.f; }
            if (t) ga_gemm(ah, al, Bs + (u32)(256 * WROW), lane, accN);
#pragma unroll
            for (int j = 0; j < 16; ++j) {
                int col = 8 * j + qc2;
                float2 gA = *(const float2*)(giA + 256 + col);
                float2 gB = *(const float2*)(giB + 256 + col);
                float b0 = sbn[col], b1 = sbn[col + 1];
                accN[j][0] = tanh_f(gA.x + accR[j][0] * (accN[j][0] + b0));
                accN[j][1] = tanh_f(gA.y + accR[j][1] * (accN[j][1] + b1));
                accN[j][2] = tanh_f(gB.x + accR[j][2] * (accN[j][2] + b0));
                accN[j][3] = tanh_f(gB.y + accR[j][3] * (accN[j][3] + b1));
            }
            // ---- z gate (reuse accR) + h update + repack frags ----
#pragma unroll
            for (int j = 0; j < 16; ++j) { accR[j][0] = accR[j][1] = accR[j][2] = accR[j][3] = 0.f; }
            if (t) ga_gemm(ah, al, Bs + (u32)(128 * WROW), lane, accR);
#pragma unroll
            for (int s = 0; s < 8; ++s) {
#pragma unroll
                for (int half = 0; half < 2; ++half) {
                    int j = 2 * s + half;
                    int col = 8 * j + qc2;
                    int fa = 4 * s + 2 * half;   // A-row frag index
                    int fb = fa + 1;             // B-row frag index
                    float2 gA = *(const float2*)(giA + 128 + col);
                    float2 gB = *(const float2*)(giB + 128 + col);
                    if (aA) {
                        float z0 = sigm_f(accR[j][0] + gA.x);
                        float z1 = sigm_f(accR[j][1] + gA.y);
                        float hp0 = lof(ah[fa]) + lof(al[fa]);
                        float hp1 = hif(ah[fa]) + hif(al[fa]);
                        float h0 = (1.f - z0) * accN[j][0] + z0 * hp0;
                        float h1 = (1.f - z1) * accN[j][1] + z1 * hp1;
                        u32 w = pk(h1, h0);
                        ah[fa] = w;
                        al[fa] = pk(h1 - hif(w), h0 - lof(w));
                    }
                    if (aB) {
                        float z2 = sigm_f(accR[j][2] + gB.x);
                        float z3 = sigm_f(accR[j][3] + gB.y);
                        float hp2 = lof(ah[fb]) + lof(al[fb]);
                        float hp3 = hif(ah[fb]) + hif(al[fb]);
                        float h2 = (1.f - z2) * accN[j][2] + z2 * hp2;
                        float h3 = (1.f - z3) * accN[j][3] + z3 * hp3;
                        u32 w = pk(h3, h2);
                        ah[fb] = w;
                        al[fb] = pk(h3 - hif(w), h2 - lof(w));
                    }
                }
            }
        }
        // write back final h frags
        u16* hA = g_hs + (size_t)iA * 256;
        u16* hB = g_hs + (size_t)iB * 256;
#pragma unroll
        for (int s = 0; s < 8; ++s) {
#pragma unroll
            for (int half = 0; half < 2; ++half) {
                int col = 8 * (2 * s + half) + qc2;
                int fa = 4 * s + 2 * half, fb = fa + 1;
                *(u32*)(hA + col) = ah[fa];  *(u32*)(hA + 128 + col) = al[fa];
                *(u32*)(hB + col) = ah[fb];  *(u32*)(hB + 128 + col) = al[fb];
            }
        }
    }
}

// ---------------- persistent final GEMM ----------------
__global__ void __launch_bounds__(256, 1) k_final_p(float* __restrict__ out) {
    extern __shared__ char sm[];
    int tid = threadIdx.x, lane = tid & 31;
    copy_w(sm, g_wself2, 128, tid);
    copy_w(sm + 128 * WROW, g_wneigh2, 128, tid);
    __syncthreads();
    u32 Bs = su32(sm);
    int qr = lane >> 2, qc2 = (lane & 3) * 2;
    while (true) {
        u32 gid;
        if (lane == 0) gid = atomicAdd(&g_wctr[2], 1);
        gid = __shfl_sync(0xFFFFFFFFu, gid, 0);
        if (gid >= NGRP) break;
        int iA = (int)gid * 16 + qr, iB = iA + 8;
        int nA = g_perm[iA], nB = g_perm[iB];
        float acc[16][4];
#pragma unroll
        for (int j = 0; j < 16; ++j) { acc[j][0] = acc[j][1] = acc[j][2] = acc[j][3] = 0.f; }
        {
            u32 ah[32], al[32];
            load_frags(g_xs + (size_t)nA * 256, g_xs + (size_t)nB * 256, qc2, ah, al);
            ga_gemm(ah, al, Bs, lane, acc);
        }
        {
            u32 ah[32], al[32];
            load_frags(g_hs + (size_t)iA * 256, g_hs + (size_t)iB * 256, qc2, ah, al);
            ga_gemm(ah, al, Bs + (u32)(128 * WROW), lane, acc);
        }
        float* oA = out + (size_t)nA * 128;
        float* oB = out + (size_t)nB * 128;
#pragma unroll
        for (int j = 0; j < 16; ++j) {
            int col = 8 * j + qc2;
            *(float2*)(oA + col) = make_float2(acc[j][0], acc[j][1]);
            *(float2*)(oB + col) = make_float2(acc[j][2], acc[j][3]);
        }
    }
}

// ---------------- launch ----------------
extern "C" void kernel_launch(void* const* d_in, const int* in_sizes, int n_in,
                              void* d_out, int out_size) {
    const float* feat    = (const float*)d_in[0];
    const float* gamma   = (const float*)d_in[1];
    const float* beta    = (const float*)d_in[2];
    const float* W_ih    = (const float*)d_in[3];
    const float* W_hh    = (const float*)d_in[4];
    const float* b_ih    = (const float*)d_in[5];
    const float* b_hh    = (const float*)d_in[6];
    const float* W_self  = (const float*)d_in[7];
    const float* W_neigh = (const float*)d_in[8];
    const int*   src     = (const int*)d_in[9];
    const void*  mask    = (const void*)d_in[10];
    float* out = (float*)d_out;

    cudaFuncSetAttribute(k_gi_p,    cudaFuncAttributeMaxDynamicSharedMemorySize, SM_GI);
    cudaFuncSetAttribute(k_scan_p,  cudaFuncAttributeMaxDynamicSharedMemorySize, SM_SC);
    cudaFuncSetAttribute(k_final_p, cudaFuncAttributeMaxDynamicSharedMemorySize, SM_FN);

    k_detect<<<1, 256>>>((const unsigned char*)mask);
    k_zero<<<1, 32>>>();
    k_stats<<<RB, 128>>>(feat);
    k_deg<<<RB, 256>>>(mask);
    k_finalize<<<1, 128>>>(gamma, beta);
    k_scatter<<<RB, 256>>>(mask);
    k_normsplit<<<(NN * 32 + 255) / 256, 256>>>(feat);
    k_wsplit<<<128, 256>>>(W_ih, W_hh, W_self, W_neigh);
    k_gi_p<<<PGRID, 256, SM_GI>>>(b_ih, b_hh);
    k_scan_p<<<PGRID, 256, SM_SC>>>(src, b_hh);
    k_final_p<<<PGRID, 256, SM_FN>>>(out);
}

// round 12
// speedup vs baseline: 3.6047x; 1.0407x over previous
#include <cuda_runtime.h>
#include <math.h>

typedef unsigned int u32;
typedef unsigned short u16;

#define NN 200000
#define MD 12
#define RB ((NN + 255) / 256)         // 782
#define NGRP (NN / 16)                // 12500 row-groups of 16
#define PGRID 148

#define WROW 528                      // padded smem row: 264 u16
#define SM_GI (384 * WROW + 1536)     // W_ih + folded biases
#define SM_SC (384 * WROW + 512 + 64) // W_hh + bhh_n + act
#define SM_FN (256 * WROW)            // W_self | W_neigh

// ---------------- scratch (device globals: allocation-free) ----------------
__device__ __align__(256) float g_gi[(size_t)NN * 384];   // x@W_ih^T + folded biases
__device__ __align__(256) u16 g_xs[(size_t)NN * 256];     // x split [hi128|lo128] bf16
__device__ __align__(256) u16 g_hs[(size_t)NN * 256];     // final h split (sorted order)
__device__ __align__(256) u16 g_wih2[384 * 256];
__device__ __align__(256) u16 g_whh2[384 * 256];
__device__ __align__(256) u16 g_wself2[128 * 256];
__device__ __align__(256) u16 g_wneigh2[128 * 256];
__device__ float g_psum[RB * 128];
__device__ float g_psq [RB * 128];
__device__ float g_a[128], g_b[128];
__device__ int   g_cnt[MD + 1], g_cur[MD + 1], g_act[MD];
__device__ int   g_perm[NN];
__device__ int   g_mtype;
__device__ u32   g_wctr[4];

__device__ __forceinline__ float sigm_f(float x) {
    return __fdividef(1.0f, 1.0f + __expf(-x));
}
__device__ __forceinline__ float tanh_f(float x) {
    return 1.0f - __fdividef(2.0f, __expf(2.0f * x) + 1.0f);
}

__device__ __forceinline__ u32 bf_rn(float v, float& asf) {
    u32 u = __float_as_uint(v);
    u32 r = (u + 0x7FFFu + ((u >> 16) & 1u)) & 0xFFFF0000u;
    asf = __uint_as_float(r);
    return r >> 16;
}
__device__ __forceinline__ u32 pk(float hi, float lo) {
    u32 d; asm("cvt.rn.bf16x2.f32 %0, %1, %2;" : "=r"(d) : "f"(hi), "f"(lo)); return d;
}
__device__ __forceinline__ float lof(u32 a) { return __uint_as_float(a << 16); }
__device__ __forceinline__ float hif(u32 a) { return __uint_as_float(a & 0xFFFF0000u); }

__device__ __forceinline__ u32 su32(const void* p) {
    return (u32)__cvta_generic_to_shared(p);
}
__device__ __forceinline__ void ldsm4(u32& r0, u32& r1, u32& r2, u32& r3, u32 a) {
    asm volatile("ldmatrix.sync.aligned.m8n8.x4.shared.b16 {%0,%1,%2,%3}, [%4];"
                 : "=r"(r0), "=r"(r1), "=r"(r2), "=r"(r3) : "r"(a));
}
__device__ __forceinline__ void mma_bf16(float* c, u32 a0, u32 a1, u32 a2, u32 a3,
                                         u32 b0, u32 b1) {
    asm volatile("mma.sync.aligned.m16n8k16.row.col.f32.bf16.bf16.f32 "
                 "{%0,%1,%2,%3}, {%4,%5,%6,%7}, {%8,%9}, {%0,%1,%2,%3};"
                 : "+f"(c[0]), "+f"(c[1]), "+f"(c[2]), "+f"(c[3])
                 : "r"(a0), "r"(a1), "r"(a2), "r"(a3), "r"(b0), "r"(b1));
}
__device__ __forceinline__ void pf_l2(const void* p) {
    asm volatile("prefetch.global.L2 [%0];" :: "l"(p));
}

// GEMM inner: held A frags (hi+lo) x resident B gate (3 products) -> acc[16][4]
__device__ __forceinline__ void ga_gemm(const u32* ah, const u32* al, u32 BsG, int lane,
                                        float acc[16][4]) {
    u32 brow = BsG + (u32)(((((lane >> 4) << 3) + (lane & 7)) * WROW) + ((lane >> 3) & 1) * 16);
#pragma unroll
    for (int s = 0; s < 8; ++s) {
        u32 a0 = ah[4*s], a1 = ah[4*s+1], a2 = ah[4*s+2], a3 = ah[4*s+3];
        u32 l0 = al[4*s], l1 = al[4*s+1], l2 = al[4*s+2], l3 = al[4*s+3];
#pragma unroll
        for (int j2 = 0; j2 < 8; ++j2) {
            u32 base = brow + (u32)(j2 * 16 * WROW + 32 * s);
            u32 b0, b1, b2, b3, c0, c1, c2, c3;
            ldsm4(b0, b1, b2, b3, base);
            ldsm4(c0, c1, c2, c3, base + 256);
            mma_bf16(acc[2*j2],   a0, a1, a2, a3, b0, b1);
            mma_bf16(acc[2*j2+1], a0, a1, a2, a3, b2, b3);
            mma_bf16(acc[2*j2],   l0, l1, l2, l3, b0, b1);
            mma_bf16(acc[2*j2+1], l0, l1, l2, l3, b2, b3);
            mma_bf16(acc[2*j2],   a0, a1, a2, a3, c0, c1);
            mma_bf16(acc[2*j2+1], a0, a1, a2, a3, c2, c3);
        }
    }
}

__device__ __forceinline__ void load_frags(const u16* rA, const u16* rB, int qc2,
                                           u32* ah, u32* al) {
#pragma unroll
    for (int s = 0; s < 8; ++s) {
        ah[4*s]   = *(const u32*)(rA + 16*s + qc2);
        ah[4*s+1] = *(const u32*)(rB + 16*s + qc2);
        ah[4*s+2] = *(const u32*)(rA + 16*s + 8 + qc2);
        ah[4*s+3] = *(const u32*)(rB + 16*s + 8 + qc2);
        al[4*s]   = *(const u32*)(rA + 128 + 16*s + qc2);
        al[4*s+1] = *(const u32*)(rB + 128 + 16*s + qc2);
        al[4*s+2] = *(const u32*)(rA + 128 + 16*s + 8 + qc2);
        al[4*s+3] = *(const u32*)(rB + 128 + 16*s + 8 + qc2);
    }
}

__device__ __forceinline__ void copy_w(char* sm, const u16* w, int rows, int tid) {
    for (int idx = tid; idx < rows * 32; idx += 256) {
        int r = idx >> 5, c = idx & 31;
        uint4 v = ((const uint4*)w)[idx];
        *(uint4*)(sm + r * WROW + c * 16) = v;
    }
}

// ---------------- mask dtype detection / setup (verified in R6/R8/R10/R11) ----------------
__global__ void k_detect(const unsigned char* __restrict__ m) {
    __shared__ int has3F, nzNot0, nz0;
    if (threadIdx.x == 0) { has3F = 0; nzNot0 = 0; nz0 = 0; }
    __syncthreads();
    for (int i = threadIdx.x; i < 16384; i += 256) {
        unsigned char b = m[i];
        if (b == 0x3F) atomicOr(&has3F, 1);
        if (b != 0 && (i & 3) != 0) atomicOr(&nzNot0, 1);
        if (b != 0 && (i & 3) == 0) atomicOr(&nz0, 1);
    }
    __syncthreads();
    if (threadIdx.x == 0) {
        int ty;
        if (has3F && nz0) ty = 3;
        else if (has3F)   ty = 2;
        else if (nzNot0)  ty = 0;
        else              ty = 1;
        g_mtype = ty;
    }
}

__device__ __forceinline__ int deg_any(const void* m, int n) {
    int ty = g_mtype;
    int d = 0;
    if (ty == 1) {
        const int* p = (const int*)m + (size_t)n * MD;
#pragma unroll
        for (int j = 0; j < MD; ++j) d += (p[j] != 0);
    } else if (ty == 0) {
        const unsigned char* p = (const unsigned char*)m + (size_t)n * MD;
#pragma unroll
        for (int j = 0; j < MD; ++j) d += (p[j] != 0);
    } else if (ty == 2) {
        const float* p = (const float*)m + (size_t)n * MD;
#pragma unroll
        for (int j = 0; j < MD; ++j) d += (p[j] != 0.0f);
    } else {
        const u16* p = (const u16*)m + (size_t)n * MD;
#pragma unroll
        for (int j = 0; j < MD; ++j) d += ((p[j] & 0x7FFF) != 0);
    }
    return d;
}

__global__ void k_zero() {
    int t = threadIdx.x;
    if (t <= MD) g_cnt[t] = 0;
    if (t < 4) g_wctr[t] = 0;
}

__global__ void k_stats(const float* __restrict__ feat) {
    int col = threadIdx.x;
    int r0 = blockIdx.x * 256;
    int rend = min(r0 + 256, NN);
    float s = 0.f, q = 0.f;
    for (int r = r0; r < rend; ++r) {
        float v = feat[(size_t)r * 128 + col];
        s += v; q += v * v;
    }
    g_psum[blockIdx.x * 128 + col] = s;
    g_psq [blockIdx.x * 128 + col] = q;
}

__global__ void k_deg(const void* __restrict__ mask) {
    __shared__ int c[MD + 1];
    int tid = threadIdx.x;
    if (tid <= MD) c[tid] = 0;
    __syncthreads();
    int n = blockIdx.x * 256 + tid;
    if (n < NN) atomicAdd(&c[deg_any(mask, n)], 1);
    __syncthreads();
    if (tid <= MD && c[tid] > 0) atomicAdd(&g_cnt[tid], c[tid]);
}

__global__ void k_finalize(const float* __restrict__ gamma, const float* __restrict__ beta) {
    int t = threadIdx.x;
    float s = 0.f, q = 0.f;
    for (int b = 0; b < RB; ++b) { s += g_psum[b * 128 + t]; q += g_psq[b * 128 + t]; }
    float mu = s * (1.0f / NN);
    float var = q * (1.0f / NN) - mu * mu;
    float rs = rsqrtf(var + 1e-5f);
    float a = rs * gamma[t];
    g_a[t] = a;
    g_b[t] = beta[t] - mu * a;
    if (t == 0) {
        int suf = 0;
        for (int d = MD; d >= 0; --d) { g_cur[d] = suf; suf += g_cnt[d]; }
        for (int sdx = 0; sdx < MD; ++sdx) g_act[sdx] = g_cur[sdx];
    }
}

__global__ void k_scatter(const void* __restrict__ mask) {
    int n = blockIdx.x * 256 + threadIdx.x;
    if (n >= NN) return;
    int pos = atomicAdd(&g_cur[deg_any(mask, n)], 1);
    g_perm[pos] = n;
}

__global__ void k_normsplit(const float* __restrict__ feat) {
    int i = blockIdx.x * 256 + threadIdx.x;
    if (i >= NN * 32) return;
    float4 v = ((const float4*)feat)[i];
    int row = i >> 5;
    int c = (i & 31) << 2;
    float f0 = v.x * g_a[c + 0] + g_b[c + 0];
    float f1 = v.y * g_a[c + 1] + g_b[c + 1];
    float f2 = v.z * g_a[c + 2] + g_b[c + 2];
    float f3 = v.w * g_a[c + 3] + g_b[c + 3];
    float h0, h1, h2, h3, d0;
    u32 a0 = bf_rn(f0, h0), a1 = bf_rn(f1, h1), a2 = bf_rn(f2, h2), a3 = bf_rn(f3, h3);
    u32 b0 = bf_rn(f0 - h0, d0), b1 = bf_rn(f1 - h1, d0), b2 = bf_rn(f2 - h2, d0), b3 = bf_rn(f3 - h3, d0);
    u16* dst = g_xs + (size_t)row * 256;
    *(uint2*)(dst + c)       = make_uint2(a0 | (a1 << 16), a2 | (a3 << 16));
    *(uint2*)(dst + 128 + c) = make_uint2(b0 | (b1 << 16), b2 | (b3 << 16));
}

__global__ void k_wsplit(const float* __restrict__ wih, const float* __restrict__ whh,
                         const float* __restrict__ wself, const float* __restrict__ wneigh) {
    int i = blockIdx.x * 256 + threadIdx.x;
    int row = i >> 5;
    int c = (i & 31) << 2;
    const float* src;
    u16* dst;
    if (row < 384)      { src = wih + (size_t)row * 128;            dst = g_wih2 + (size_t)row * 256; }
    else if (row < 768) { src = whh + (size_t)(row - 384) * 128;    dst = g_whh2 + (size_t)(row - 384) * 256; }
    else if (row < 896) { src = wself + (size_t)(row - 768) * 128;  dst = g_wself2 + (size_t)(row - 768) * 256; }
    else                { src = wneigh + (size_t)(row - 896) * 128; dst = g_wneigh2 + (size_t)(row - 896) * 256; }
    float4 v = *(const float4*)(src + c);
    float h0, h1, h2, h3, dm;
    u32 a0 = bf_rn(v.x, h0), a1 = bf_rn(v.y, h1), a2 = bf_rn(v.z, h2), a3 = bf_rn(v.w, h3);
    u32 b0 = bf_rn(v.x - h0, dm), b1 = bf_rn(v.y - h1, dm), b2 = bf_rn(v.z - h2, dm), b3 = bf_rn(v.w - h3, dm);
    *(uint2*)(dst + c)       = make_uint2(a0 | (a1 << 16), a2 | (a3 << 16));
    *(uint2*)(dst + 128 + c) = make_uint2(b0 | (b1 << 16), b2 | (b3 << 16));
}

// ---------------- persistent gi GEMM: g_gi = x @ W_ih^T + folded biases ----------------
__global__ void __launch_bounds__(256, 1) k_gi_p(const float* __restrict__ bih,
                                                 const float* __restrict__ bhh) {
    extern __shared__ char sm[];
    int tid = threadIdx.x, lane = tid & 31;
    copy_w(sm, g_wih2, 384, tid);
    float* sb = (float*)(sm + 384 * WROW);
    for (int j = tid; j < 384; j += 256)
        sb[j] = bih[j] + (j < 256 ? bhh[j] : 0.f);
    __syncthreads();
    u32 Bs = su32(sm);
    int qr = lane >> 2, qc2 = (lane & 3) * 2;
    while (true) {
        u32 gid;
        if (lane == 0) gid = atomicAdd(&g_wctr[0], 1);
        gid = __shfl_sync(0xFFFFFFFFu, gid, 0);
        if (gid >= NGRP) break;
        int iA = gid * 16 + qr, iB = iA + 8;
        const u16* rA = g_xs + (size_t)iA * 256;
        const u16* rB = g_xs + (size_t)iB * 256;
        u32 ah[32], al[32];
        load_frags(rA, rB, qc2, ah, al);
        float* oA = g_gi + (size_t)iA * 384;
        float* oB = g_gi + (size_t)iB * 384;
#pragma unroll 1
        for (int g = 0; g < 3; ++g) {
            float acc[16][4];
#pragma unroll
            for (int j = 0; j < 16; ++j) { acc[j][0] = acc[j][1] = acc[j][2] = acc[j][3] = 0.f; }
            ga_gemm(ah, al, Bs + (u32)(g * 128 * WROW), lane, acc);
#pragma unroll
            for (int j = 0; j < 16; ++j) {
                int col = g * 128 + 8 * j + qc2;
                float b0 = sb[col], b1 = sb[col + 1];
                *(float2*)(oA + col) = make_float2(acc[j][0] + b0, acc[j][1] + b1);
                *(float2*)(oB + col) = make_float2(acc[j][2] + b0, acc[j][3] + b1);
            }
        }
    }
}

// ---------------- persistent 12-step GRU scan (h as split-bf16 A-frags, L2 prefetch) ----------------
__global__ void __launch_bounds__(256, 1) k_scan_p(const int* __restrict__ src,
                                                   const float* __restrict__ bhh) {
    extern __shared__ char sm[];
    int tid = threadIdx.x, lane = tid & 31;
    copy_w(sm, g_whh2, 384, tid);
    float* sbn = (float*)(sm + 384 * WROW);
    int* sact = (int*)(sbn + 128);
    if (tid < 128) sbn[tid] = bhh[256 + tid];
    if (tid < MD) sact[tid] = g_act[tid];
    __syncthreads();
    u32 Bs = su32(sm);
    int qr = lane >> 2, qc2 = (lane & 3) * 2;
    int pfo = (lane & 3) * 384;          // per-lane prefetch offset within a 1536B gi row
    while (true) {
        u32 gid;
        if (lane == 0) gid = atomicAdd(&g_wctr[1], 1);
        gid = __shfl_sync(0xFFFFFFFFu, gid, 0);
        if (gid >= NGRP) break;
        int i0 = (int)gid * 16;
        int iA = i0 + qr, iB = iA + 8;
        int nA = g_perm[iA], nB = g_perm[iB];
        const int* sAp = src + (size_t)nA * MD;
        const int* sBp = src + (size_t)nB * MD;
        // prefetch step 0 rows immediately
        if (sact[0] > i0) {
            const char* qA = (const char*)(g_gi + (size_t)__ldg(sAp) * 384) + pfo;
            const char* qB = (const char*)(g_gi + (size_t)__ldg(sBp) * 384) + pfo;
            pf_l2(qA); pf_l2(qA + 128); pf_l2(qA + 256);
            pf_l2(qB); pf_l2(qB + 128); pf_l2(qB + 256);
        }
        u32 ah[32], al[32];                 // h state as split-bf16 mma A-fragments
#pragma unroll
        for (int k = 0; k < 32; ++k) { ah[k] = 0u; al[k] = 0u; }
#pragma unroll 1
        for (int t = 0; t < MD; ++t) {
            int actT = sact[t];
            if (actT <= i0) break;
            bool aA = iA < actT, aB = iB < actT;
            int sA = __ldg(sAp + t), sB = __ldg(sBp + t);
            const float* giA = g_gi + (size_t)sA * 384;
            const float* giB = g_gi + (size_t)sB * 384;
            // prefetch next step's gi rows into L2 (hidden behind 3 gate GEMMs)
            if (t + 1 < MD && sact[t + 1] > i0) {
                const char* qA = (const char*)(g_gi + (size_t)__ldg(sAp + t + 1) * 384) + pfo;
                const char* qB = (const char*)(g_gi + (size_t)__ldg(sBp + t + 1) * 384) + pfo;
                pf_l2(qA); pf_l2(qA + 128); pf_l2(qA + 256);
                pf_l2(qB); pf_l2(qB + 128); pf_l2(qB + 256);
            }
            // ---- r gate ----
            float accR[16][4];
#pragma unroll
            for (int j = 0; j < 16; ++j) { accR[j][0] = accR[j][1] = accR[j][2] = accR[j][3] = 0.f; }
            if (t) ga_gemm(ah, al, Bs, lane, accR);
#pragma unroll
            for (int j = 0; j < 16; ++j) {
                int col = 8 * j + qc2;
                float2 gA = *(const float2*)(giA + col);
                float2 gB = *(const float2*)(giB + col);
                accR[j][0] = sigm_f(accR[j][0] + gA.x);
                accR[j][1] = sigm_f(accR[j][1] + gA.y);
                accR[j][2] = sigm_f(accR[j][2] + gB.x);
                accR[j][3] = sigm_f(accR[j][3] + gB.y);
            }
            // ---- n gate ----
            float accN[16][4];
#pragma unroll
            for (int j = 0; j < 16; ++j) { accN[j][0] = accN[j][1] = accN[j][2] = accN[j][3] = 0.f; }
            if (t) ga_gemm(ah, al, Bs + (u32)(256 * WROW), lane, accN);
#pragma unroll
            for (int j = 0; j < 16; ++j) {
                int col = 8 * j + qc2;
                float2 gA = *(const float2*)(giA + 256 + col);
                float2 gB = *(const float2*)(giB + 256 + col);
                float b0 = sbn[col], b1 = sbn[col + 1];
                accN[j][0] = tanh_f(gA.x + accR[j][0] * (accN[j][0] + b0));
                accN[j][1] = tanh_f(gA.y + accR[j][1] * (accN[j][1] + b1));
                accN[j][2] = tanh_f(gB.x + accR[j][2] * (accN[j][2] + b0));
                accN[j][3] = tanh_f(gB.y + accR[j][3] * (accN[j][3] + b1));
            }
            // ---- z gate (reuse accR) + h update + repack frags ----
#pragma unroll
            for (int j = 0; j < 16; ++j) { accR[j][0] = accR[j][1] = accR[j][2] = accR[j][3] = 0.f; }
            if (t) ga_gemm(ah, al, Bs + (u32)(128 * WROW), lane, accR);
#pragma unroll
            for (int s = 0; s < 8; ++s) {
#pragma unroll
                for (int half = 0; half < 2; ++half) {
                    int j = 2 * s + half;
                    int col = 8 * j + qc2;
                    int fa = 4 * s + 2 * half;
                    int fb = fa + 1;
                    float2 gA = *(const float2*)(giA + 128 + col);
                    float2 gB = *(const float2*)(giB + 128 + col);
                    if (aA) {
                        float z0 = sigm_f(accR[j][0] + gA.x);
                        float z1 = sigm_f(accR[j][1] + gA.y);
                        float hp0 = lof(ah[fa]) + lof(al[fa]);
                        float hp1 = hif(ah[fa]) + hif(al[fa]);
                        float h0 = (1.f - z0) * accN[j][0] + z0 * hp0;
                        float h1 = (1.f - z1) * accN[j][1] + z1 * hp1;
                        u32 w = pk(h1, h0);
                        ah[fa] = w;
                        al[fa] = pk(h1 - hif(w), h0 - lof(w));
                    }
                    if (aB) {
                        float z2 = sigm_f(accR[j][2] + gB.x);
                        float z3 = sigm_f(accR[j][3] + gB.y);
                        float hp2 = lof(ah[fb]) + lof(al[fb]);
                        float hp3 = hif(ah[fb]) + hif(al[fb]);
                        float h2 = (1.f - z2) * accN[j][2] + z2 * hp2;
                        float h3 = (1.f - z3) * accN[j][3] + z3 * hp3;
                        u32 w = pk(h3, h2);
                        ah[fb] = w;
                        al[fb] = pk(h3 - hif(w), h2 - lof(w));
                    }
                }
            }
        }
        // write back final h frags
        u16* hA = g_hs + (size_t)iA * 256;
        u16* hB = g_hs + (size_t)iB * 256;
#pragma unroll
        for (int s = 0; s < 8; ++s) {
#pragma unroll
            for (int half = 0; half < 2; ++half) {
                int col = 8 * (2 * s + half) + qc2;
                int fa = 4 * s + 2 * half, fb = fa + 1;
                *(u32*)(hA + col) = ah[fa];  *(u32*)(hA + 128 + col) = al[fa];
                *(u32*)(hB + col) = ah[fb];  *(u32*)(hB + 128 + col) = al[fb];
            }
        }
    }
}

// ---------------- persistent final GEMM ----------------
__global__ void __launch_bounds__(256, 1) k_final_p(float* __restrict__ out) {
    extern __shared__ char sm[];
    int tid = threadIdx.x, lane = tid & 31;
    copy_w(sm, g_wself2, 128, tid);
    copy_w(sm + 128 * WROW, g_wneigh2, 128, tid);
    __syncthreads();
    u32 Bs = su32(sm);
    int qr = lane >> 2, qc2 = (lane & 3) * 2;
    while (true) {
        u32 gid;
        if (lane == 0) gid = atomicAdd(&g_wctr[2], 1);
        gid = __shfl_sync(0xFFFFFFFFu, gid, 0);
        if (gid >= NGRP) break;
        int iA = (int)gid * 16 + qr, iB = iA + 8;
        int nA = g_perm[iA], nB = g_perm[iB];
        float acc[16][4];
#pragma unroll
        for (int j = 0; j < 16; ++j) { acc[j][0] = acc[j][1] = acc[j][2] = acc[j][3] = 0.f; }
        {
            u32 ah[32], al[32];
            load_frags(g_xs + (size_t)nA * 256, g_xs + (size_t)nB * 256, qc2, ah, al);
            ga_gemm(ah, al, Bs, lane, acc);
        }
        {
            u32 ah[32], al[32];
            load_frags(g_hs + (size_t)iA * 256, g_hs + (size_t)iB * 256, qc2, ah, al);
            ga_gemm(ah, al, Bs + (u32)(128 * WROW), lane, acc);
        }
        float* oA = out + (size_t)nA * 128;
        float* oB = out + (size_t)nB * 128;
#pragma unroll
        for (int j = 0; j < 16; ++j) {
            int col = 8 * j + qc2;
            *(float2*)(oA + col) = make_float2(acc[j][0], acc[j][1]);
            *(float2*)(oB + col) = make_float2(acc[j][2], acc[j][3]);
        }
    }
}

// ---------------- launch ----------------
extern "C" void kernel_launch(void* const* d_in, const int* in_sizes, int n_in,
                              void* d_out, int out_size) {
    const float* feat    = (const float*)d_in[0];
    const float* gamma   = (const float*)d_in[1];
    const float* beta    = (const float*)d_in[2];
    const float* W_ih    = (const float*)d_in[3];
    const float* W_hh    = (const float*)d_in[4];
    const float* b_ih    = (const float*)d_in[5];
    const float* b_hh    = (const float*)d_in[6];
    const float* W_self  = (const float*)d_in[7];
    const float* W_neigh = (const float*)d_in[8];
    const int*   src     = (const int*)d_in[9];
    const void*  mask    = (const void*)d_in[10];
    float* out = (float*)d_out;

    cudaFuncSetAttribute(k_gi_p,    cudaFuncAttributeMaxDynamicSharedMemorySize, SM_GI);
    cudaFuncSetAttribute(k_scan_p,  cudaFuncAttributeMaxDynamicSharedMemorySize, SM_SC);
    cudaFuncSetAttribute(k_final_p, cudaFuncAttributeMaxDynamicSharedMemorySize, SM_FN);

    k_detect<<<1, 256>>>((const unsigned char*)mask);
    k_zero<<<1, 32>>>();
    k_stats<<<RB, 128>>>(feat);
    k_deg<<<RB, 256>>>(mask);
    k_finalize<<<1, 128>>>(gamma, beta);
    k_scatter<<<RB, 256>>>(mask);
    k_normsplit<<<(NN * 32 + 255) / 256, 256>>>(feat);
    k_wsplit<<<128, 256>>>(W_ih, W_hh, W_self, W_neigh);
    k_gi_p<<<PGRID, 256, SM_GI>>>(b_ih, b_hh);
    k_scan_p<<<PGRID, 256, SM_SC>>>(src, b_hh);
    k_final_p<<<PGRID, 256, SM_FN>>>(out);
}

// round 15
// speedup vs baseline: 4.6864x; 1.3001x over previous
#include <cuda_runtime.h>
#include <math.h>

typedef unsigned int u32;
typedef unsigned short u16;

#define NN 200000
#define MD 12
#define RB ((NN + 255) / 256)         // 782
#define NGRP (NN / 16)                // 12500 row-groups of 16
#define PGRID 148

#define WROW 528                      // padded smem row: 264 u16 (bf16-split weights)
#define WROWH 272                     // padded smem row: 136 u16 (fp16 weights)
#define SM_GI (384 * WROW + 1536)     // W_ih + folded biases
#define SM_SC (384 * WROWH + 512 + 64)// W_hh fp16 + bhh_n + act
#define SM_FN (128 * WROW + 128 * WROWH) // W_self bf16split | W_neigh fp16

// ---------------- scratch (device globals: allocation-free) ----------------
__device__ __align__(256) float g_gi[(size_t)NN * 384];   // x@W_ih^T + folded biases
__device__ __align__(256) u16 g_xs[(size_t)NN * 256];     // x split [hi128|lo128] bf16
__device__ __align__(256) u16 g_hs[(size_t)NN * 128];     // final h (fp16, sorted order)
__device__ __align__(256) u16 g_wih2[384 * 256];          // W_ih bf16 split
__device__ __align__(256) u16 g_wself2[128 * 256];        // W_self bf16 split
__device__ __align__(256) u16 g_whhh[384 * 128];          // W_hh fp16
__device__ __align__(256) u16 g_wnhh[128 * 128];          // W_neigh fp16
__device__ float g_psum[RB * 128];
__device__ float g_psq [RB * 128];
__device__ float g_a[128], g_b[128];
__device__ int   g_cnt[MD + 1], g_cur[MD + 1], g_act[MD];
__device__ int   g_perm[NN];
__device__ int   g_mtype;
__device__ u32   g_wctr[4];

__device__ __forceinline__ float sigm_f(float x) {
    return __fdividef(1.0f, 1.0f + __expf(-x));
}
__device__ __forceinline__ float tanh_f(float x) {
    return 1.0f - __fdividef(2.0f, __expf(2.0f * x) + 1.0f);
}

__device__ __forceinline__ u32 bf_rn(float v, float& asf) {
    u32 u = __float_as_uint(v);
    u32 r = (u + 0x7FFFu + ((u >> 16) & 1u)) & 0xFFFF0000u;
    asf = __uint_as_float(r);
    return r >> 16;
}
// fp16x2 pack/unpack
__device__ __forceinline__ u32 pkh(float hi, float lo) {
    u32 d; asm("cvt.rn.f16x2.f32 %0, %1, %2;" : "=r"(d) : "f"(hi), "f"(lo)); return d;
}
__device__ __forceinline__ float lofh(u32 a) {
    float f;
    asm("{\n\t.reg .b16 l,h;\n\tmov.b32 {l,h}, %1;\n\tcvt.f32.f16 %0, l;\n\t}"
        : "=f"(f) : "r"(a));
    return f;
}
__device__ __forceinline__ float hifh(u32 a) {
    float f;
    asm("{\n\t.reg .b16 l,h;\n\tmov.b32 {l,h}, %1;\n\tcvt.f32.f16 %0, h;\n\t}"
        : "=f"(f) : "r"(a));
    return f;
}

__device__ __forceinline__ u32 su32(const void* p) {
    return (u32)__cvta_generic_to_shared(p);
}
__device__ __forceinline__ void ldsm4(u32& r0, u32& r1, u32& r2, u32& r3, u32 a) {
    asm volatile("ldmatrix.sync.aligned.m8n8.x4.shared.b16 {%0,%1,%2,%3}, [%4];"
                 : "=r"(r0), "=r"(r1), "=r"(r2), "=r"(r3) : "r"(a));
}
__device__ __forceinline__ void mma_bf16(float* c, u32 a0, u32 a1, u32 a2, u32 a3,
                                         u32 b0, u32 b1) {
    asm volatile("mma.sync.aligned.m16n8k16.row.col.f32.bf16.bf16.f32 "
                 "{%0,%1,%2,%3}, {%4,%5,%6,%7}, {%8,%9}, {%0,%1,%2,%3};"
                 : "+f"(c[0]), "+f"(c[1]), "+f"(c[2]), "+f"(c[3])
                 : "r"(a0), "r"(a1), "r"(a2), "r"(a3), "r"(b0), "r"(b1));
}
__device__ __forceinline__ void mma_f16(float* c, u32 a0, u32 a1, u32 a2, u32 a3,
                                        u32 b0, u32 b1) {
    asm volatile("mma.sync.aligned.m16n8k16.row.col.f32.f16.f16.f32 "
                 "{%0,%1,%2,%3}, {%4,%5,%6,%7}, {%8,%9}, {%0,%1,%2,%3};"
                 : "+f"(c[0]), "+f"(c[1]), "+f"(c[2]), "+f"(c[3])
                 : "r"(a0), "r"(a1), "r"(a2), "r"(a3), "r"(b0), "r"(b1));
}
__device__ __forceinline__ void pf_l2(const void* p) {
    asm volatile("prefetch.global.L2 [%0];" :: "l"(p));
}

// bf16 split GEMM (3 products) — x-side; B rows are 256 u16 wide (WROW stride)
__device__ __forceinline__ void ga_gemm(const u32* ah, const u32* al, u32 BsG, int lane,
                                        float acc[16][4]) {
    u32 brow = BsG + (u32)(((((lane >> 4) << 3) + (lane & 7)) * WROW) + ((lane >> 3) & 1) * 16);
#pragma unroll
    for (int s = 0; s < 8; ++s) {
        u32 a0 = ah[4*s], a1 = ah[4*s+1], a2 = ah[4*s+2], a3 = ah[4*s+3];
        u32 l0 = al[4*s], l1 = al[4*s+1], l2 = al[4*s+2], l3 = al[4*s+3];
#pragma unroll
        for (int j2 = 0; j2 < 8; ++j2) {
            u32 base = brow + (u32)(j2 * 16 * WROW + 32 * s);
            u32 b0, b1, b2, b3, c0, c1, c2, c3;
            ldsm4(b0, b1, b2, b3, base);
            ldsm4(c0, c1, c2, c3, base + 256);
            mma_bf16(acc[2*j2],   a0, a1, a2, a3, b0, b1);
            mma_bf16(acc[2*j2+1], a0, a1, a2, a3, b2, b3);
            mma_bf16(acc[2*j2],   l0, l1, l2, l3, b0, b1);
            mma_bf16(acc[2*j2+1], l0, l1, l2, l3, b2, b3);
            mma_bf16(acc[2*j2],   a0, a1, a2, a3, c0, c1);
            mma_bf16(acc[2*j2+1], a0, a1, a2, a3, c2, c3);
        }
    }
}

// fp16 single-product GEMM — h-side; B rows are 128 u16 wide (WROWH stride)
__device__ __forceinline__ void gh1_gemm(const u32* ah, u32 BsG, int lane,
                                         float acc[16][4]) {
    u32 brow = BsG + (u32)(((((lane >> 4) << 3) + (lane & 7)) * WROWH) + ((lane >> 3) & 1) * 16);
#pragma unroll
    for (int s = 0; s < 8; ++s) {
        u32 a0 = ah[4*s], a1 = ah[4*s+1], a2 = ah[4*s+2], a3 = ah[4*s+3];
#pragma unroll
        for (int j2 = 0; j2 < 8; ++j2) {
            u32 base = brow + (u32)(j2 * 16 * WROWH + 32 * s);
            u32 b0, b1, b2, b3;
            ldsm4(b0, b1, b2, b3, base);
            mma_f16(acc[2*j2],   a0, a1, a2, a3, b0, b1);
            mma_f16(acc[2*j2+1], a0, a1, a2, a3, b2, b3);
        }
    }
}

__device__ __forceinline__ void load_frags(const u16* rA, const u16* rB, int qc2,
                                           u32* ah, u32* al) {
#pragma unroll
    for (int s = 0; s < 8; ++s) {
        ah[4*s]   = *(const u32*)(rA + 16*s + qc2);
        ah[4*s+1] = *(const u32*)(rB + 16*s + qc2);
        ah[4*s+2] = *(const u32*)(rA + 16*s + 8 + qc2);
        ah[4*s+3] = *(const u32*)(rB + 16*s + 8 + qc2);
        al[4*s]   = *(const u32*)(rA + 128 + 16*s + qc2);
        al[4*s+1] = *(const u32*)(rB + 128 + 16*s + qc2);
        al[4*s+2] = *(const u32*)(rA + 128 + 16*s + 8 + qc2);
        al[4*s+3] = *(const u32*)(rB + 128 + 16*s + 8 + qc2);
    }
}
// fp16 h rows: 128 u16 wide
__device__ __forceinline__ void load_frags_h(const u16* rA, const u16* rB, int qc2, u32* ah) {
#pragma unroll
    for (int s = 0; s < 8; ++s) {
        ah[4*s]   = *(const u32*)(rA + 16*s + qc2);
        ah[4*s+1] = *(const u32*)(rB + 16*s + qc2);
        ah[4*s+2] = *(const u32*)(rA + 16*s + 8 + qc2);
        ah[4*s+3] = *(const u32*)(rB + 16*s + 8 + qc2);
    }
}

__device__ __forceinline__ void copy_w(char* sm, const u16* w, int rows, int tid) {
    for (int idx = tid; idx < rows * 32; idx += 256) {
        int r = idx >> 5, c = idx & 31;
        uint4 v = ((const uint4*)w)[idx];
        *(uint4*)(sm + r * WROW + c * 16) = v;
    }
}
__device__ __forceinline__ void copy_wh(char* sm, const u16* w, int rows, int tid) {
    for (int idx = tid; idx < rows * 16; idx += 256) {
        int r = idx >> 4, c = idx & 15;
        uint4 v = ((const uint4*)w)[idx];
        *(uint4*)(sm + r * WROWH + c * 16) = v;
    }
}

// ---------------- mask dtype detection / setup (verified R6..R12) ----------------
__global__ void k_detect(const unsigned char* __restrict__ m) {
    __shared__ int has3F, nzNot0, nz0;
    if (threadIdx.x == 0) { has3F = 0; nzNot0 = 0; nz0 = 0; }
    __syncthreads();
    for (int i = threadIdx.x; i < 16384; i += 256) {
        unsigned char b = m[i];
        if (b == 0x3F) atomicOr(&has3F, 1);
        if (b != 0 && (i & 3) != 0) atomicOr(&nzNot0, 1);
        if (b != 0 && (i & 3) == 0) atomicOr(&nz0, 1);
    }
    __syncthreads();
    if (threadIdx.x == 0) {
        int ty;
        if (has3F && nz0) ty = 3;
        else if (has3F)   ty = 2;
        else if (nzNot0)  ty = 0;
        else              ty = 1;
        g_mtype = ty;
    }
}

__device__ __forceinline__ int deg_any(const void* m, int n) {
    int ty = g_mtype;
    int d = 0;
    if (ty == 1) {
        const int* p = (const int*)m + (size_t)n * MD;
#pragma unroll
        for (int j = 0; j < MD; ++j) d += (p[j] != 0);
    } else if (ty == 0) {
        const unsigned char* p = (const unsigned char*)m + (size_t)n * MD;
#pragma unroll
        for (int j = 0; j < MD; ++j) d += (p[j] != 0);
    } else if (ty == 2) {
        const float* p = (const float*)m + (size_t)n * MD;
#pragma unroll
        for (int j = 0; j < MD; ++j) d += (p[j] != 0.0f);
    } else {
        const u16* p = (const u16*)m + (size_t)n * MD;
#pragma unroll
        for (int j = 0; j < MD; ++j) d += ((p[j] & 0x7FFF) != 0);
    }
    return d;
}

__global__ void k_zero() {
    int t = threadIdx.x;
    if (t <= MD) g_cnt[t] = 0;
    if (t < 4) g_wctr[t] = 0;
}

__global__ void k_stats(const float* __restrict__ feat) {
    int col = threadIdx.x;
    int r0 = blockIdx.x * 256;
    int rend = min(r0 + 256, NN);
    float s = 0.f, q = 0.f;
    for (int r = r0; r < rend; ++r) {
        float v = feat[(size_t)r * 128 + col];
        s += v; q += v * v;
    }
    g_psum[blockIdx.x * 128 + col] = s;
    g_psq [blockIdx.x * 128 + col] = q;
}

__global__ void k_deg(const void* __restrict__ mask) {
    __shared__ int c[MD + 1];
    int tid = threadIdx.x;
    if (tid <= MD) c[tid] = 0;
    __syncthreads();
    int n = blockIdx.x * 256 + tid;
    if (n < NN) atomicAdd(&c[deg_any(mask, n)], 1);
    __syncthreads();
    if (tid <= MD && c[tid] > 0) atomicAdd(&g_cnt[tid], c[tid]);
}

__global__ void k_finalize(const float* __restrict__ gamma, const float* __restrict__ beta) {
    int t = threadIdx.x;
    float s = 0.f, q = 0.f;
    for (int b = 0; b < RB; ++b) { s += g_psum[b * 128 + t]; q += g_psq[b * 128 + t]; }
    float mu = s * (1.0f / NN);
    float var = q * (1.0f / NN) - mu * mu;
    float rs = rsqrtf(var + 1e-5f);
    float a = rs * gamma[t];
    g_a[t] = a;
    g_b[t] = beta[t] - mu * a;
    if (t == 0) {
        int suf = 0;
        for (int d = MD; d >= 0; --d) { g_cur[d] = suf; suf += g_cnt[d]; }
        for (int sdx = 0; sdx < MD; ++sdx) g_act[sdx] = g_cur[sdx];
    }
}

__global__ void k_scatter(const void* __restrict__ mask) {
    int n = blockIdx.x * 256 + threadIdx.x;
    if (n >= NN) return;
    int pos = atomicAdd(&g_cur[deg_any(mask, n)], 1);
    g_perm[pos] = n;
}

__global__ void k_normsplit(const float* __restrict__ feat) {
    int i = blockIdx.x * 256 + threadIdx.x;
    if (i >= NN * 32) return;
    float4 v = ((const float4*)feat)[i];
    int row = i >> 5;
    int c = (i & 31) << 2;
    float f0 = v.x * g_a[c + 0] + g_b[c + 0];
    float f1 = v.y * g_a[c + 1] + g_b[c + 1];
    float f2 = v.z * g_a[c + 2] + g_b[c + 2];
    float f3 = v.w * g_a[c + 3] + g_b[c + 3];
    float h0, h1, h2, h3, d0;
    u32 a0 = bf_rn(f0, h0), a1 = bf_rn(f1, h1), a2 = bf_rn(f2, h2), a3 = bf_rn(f3, h3);
    u32 b0 = bf_rn(f0 - h0, d0), b1 = bf_rn(f1 - h1, d0), b2 = bf_rn(f2 - h2, d0), b3 = bf_rn(f3 - h3, d0);
    u16* dst = g_xs + (size_t)row * 256;
    *(uint2*)(dst + c)       = make_uint2(a0 | (a1 << 16), a2 | (a3 << 16));
    *(uint2*)(dst + 128 + c) = make_uint2(b0 | (b1 << 16), b2 | (b3 << 16));
}

// bf16-split conversion: 512 rows (384 Wih, 128 Wself)
__global__ void k_wsplit(const float* __restrict__ wih, const float* __restrict__ wself) {
    int i = blockIdx.x * 256 + threadIdx.x;
    if (i >= 512 * 32) return;
    int row = i >> 5;
    int c = (i & 31) << 2;
    const float* src;
    u16* dst;
    if (row < 384) { src = wih + (size_t)row * 128;           dst = g_wih2 + (size_t)row * 256; }
    else           { src = wself + (size_t)(row - 384) * 128; dst = g_wself2 + (size_t)(row - 384) * 256; }
    float4 v = *(const float4*)(src + c);
    float h0, h1, h2, h3, dm;
    u32 a0 = bf_rn(v.x, h0), a1 = bf_rn(v.y, h1), a2 = bf_rn(v.z, h2), a3 = bf_rn(v.w, h3);
    u32 b0 = bf_rn(v.x - h0, dm), b1 = bf_rn(v.y - h1, dm), b2 = bf_rn(v.z - h2, dm), b3 = bf_rn(v.w - h3, dm);
    *(uint2*)(dst + c)       = make_uint2(a0 | (a1 << 16), a2 | (a3 << 16));
    *(uint2*)(dst + 128 + c) = make_uint2(b0 | (b1 << 16), b2 | (b3 << 16));
}

// fp16 conversion: 512 rows (384 Whh, 128 Wneigh), one thread per float2
__global__ void k_whalf(const float* __restrict__ whh, const float* __restrict__ wneigh) {
    int i = blockIdx.x * 256 + threadIdx.x;
    if (i >= 512 * 64) return;
    int row = i >> 6;
    int c2 = (i & 63) * 2;
    const float* s;
    u16* d;
    if (row < 384) { s = whh + (size_t)row * 128;            d = g_whhh + (size_t)row * 128; }
    else           { s = wneigh + (size_t)(row - 384) * 128; d = g_wnhh + (size_t)(row - 384) * 128; }
    float2 v = *(const float2*)(s + c2);
    *(u32*)(d + c2) = pkh(v.y, v.x);
}

// ---------------- persistent gi GEMM: g_gi = x @ W_ih^T + folded biases ----------------
__global__ void __launch_bounds__(256, 1) k_gi_p(const float* __restrict__ bih,
                                                 const float* __restrict__ bhh) {
    extern __shared__ char sm[];
    int tid = threadIdx.x, lane = tid & 31;
    copy_w(sm, g_wih2, 384, tid);
    float* sb = (float*)(sm + 384 * WROW);
    for (int j = tid; j < 384; j += 256)
        sb[j] = bih[j] + (j < 256 ? bhh[j] : 0.f);
    __syncthreads();
    u32 Bs = su32(sm);
    int qr = lane >> 2, qc2 = (lane & 3) * 2;
    while (true) {
        u32 gid;
        if (lane == 0) gid = atomicAdd(&g_wctr[0], 1);
        gid = __shfl_sync(0xFFFFFFFFu, gid, 0);
        if (gid >= NGRP) break;
        int iA = gid * 16 + qr, iB = iA + 8;
        u32 ah[32], al[32];
        load_frags(g_xs + (size_t)iA * 256, g_xs + (size_t)iB * 256, qc2, ah, al);
        float* oA = g_gi + (size_t)iA * 384;
        float* oB = g_gi + (size_t)iB * 384;
#pragma unroll 1
        for (int g = 0; g < 3; ++g) {
            float acc[16][4];
#pragma unroll
            for (int j = 0; j < 16; ++j) { acc[j][0] = acc[j][1] = acc[j][2] = acc[j][3] = 0.f; }
            ga_gemm(ah, al, Bs + (u32)(g * 128 * WROW), lane, acc);
#pragma unroll
            for (int j = 0; j < 16; ++j) {
                int col = g * 128 + 8 * j + qc2;
                float b0 = sb[col], b1 = sb[col + 1];
                *(float2*)(oA + col) = make_float2(acc[j][0] + b0, acc[j][1] + b1);
                *(float2*)(oB + col) = make_float2(acc[j][2] + b0, acc[j][3] + b1);
            }
        }
    }
}

// ---------------- persistent 12-step GRU scan (fp16 h frags, single-product gh) ----------------
__global__ void __launch_bounds__(256, 1) k_scan_p(const int* __restrict__ src,
                                                   const float* __restrict__ bhh) {
    extern __shared__ char sm[];
    int tid = threadIdx.x, lane = tid & 31;
    copy_wh(sm, g_whhh, 384, tid);
    float* sbn = (float*)(sm + 384 * WROWH);
    int* sact = (int*)(sbn + 128);
    if (tid < 128) sbn[tid] = bhh[256 + tid];
    if (tid < MD) sact[tid] = g_act[tid];
    __syncthreads();
    u32 Bs = su32(sm);
    int qr = lane >> 2, qc2 = (lane & 3) * 2;
    int pfo = (lane & 3) * 384;
    while (true) {
        u32 gid;
        if (lane == 0) gid = atomicAdd(&g_wctr[1], 1);
        gid = __shfl_sync(0xFFFFFFFFu, gid, 0);
        if (gid >= NGRP) break;
        int i0 = (int)gid * 16;
        int iA = i0 + qr, iB = iA + 8;
        int nA = g_perm[iA], nB = g_perm[iB];
        const int* sAp = src + (size_t)nA * MD;
        const int* sBp = src + (size_t)nB * MD;
        if (sact[0] > i0) {
            const char* qA = (const char*)(g_gi + (size_t)__ldg(sAp) * 384) + pfo;
            const char* qB = (const char*)(g_gi + (size_t)__ldg(sBp) * 384) + pfo;
            pf_l2(qA); pf_l2(qA + 128); pf_l2(qA + 256);
            pf_l2(qB); pf_l2(qB + 128); pf_l2(qB + 256);
        }
        u32 ah[32];                 // h state as fp16 mma A-fragments
#pragma unroll
        for (int k = 0; k < 32; ++k) ah[k] = 0u;
#pragma unroll 1
        for (int t = 0; t < MD; ++t) {
            int actT = sact[t];
            if (actT <= i0) break;
            bool aA = iA < actT, aB = iB < actT;
            int sA = __ldg(sAp + t), sB = __ldg(sBp + t);
            const float* giA = g_gi + (size_t)sA * 384;
            const float* giB = g_gi + (size_t)sB * 384;
            if (t + 1 < MD && sact[t + 1] > i0) {
                const char* qA = (const char*)(g_gi + (size_t)__ldg(sAp + t + 1) * 384) + pfo;
                const char* qB = (const char*)(g_gi + (size_t)__ldg(sBp + t + 1) * 384) + pfo;
                pf_l2(qA); pf_l2(qA + 128); pf_l2(qA + 256);
                pf_l2(qB); pf_l2(qB + 128); pf_l2(qB + 256);
            }
            // ---- r gate ----
            float accR[16][4];
#pragma unroll
            for (int j = 0; j < 16; ++j) { accR[j][0] = accR[j][1] = accR[j][2] = accR[j][3] = 0.f; }
            if (t) gh1_gemm(ah, Bs, lane, accR);
#pragma unroll
            for (int j = 0; j < 16; ++j) {
                int col = 8 * j + qc2;
                float2 gA = *(const float2*)(giA + col);
                float2 gB = *(const float2*)(giB + col);
                accR[j][0] = sigm_f(accR[j][0] + gA.x);
                accR[j][1] = sigm_f(accR[j][1] + gA.y);
                accR[j][2] = sigm_f(accR[j][2] + gB.x);
                accR[j][3] = sigm_f(accR[j][3] + gB.y);
            }
            // ---- n gate ----
            float accN[16][4];
#pragma unroll
            for (int j = 0; j < 16; ++j) { accN[j][0] = accN[j][1] = accN[j][2] = accN[j][3] = 0.f; }
            if (t) gh1_gemm(ah, Bs + (u32)(256 * WROWH), lane, accN);
#pragma unroll
            for (int j = 0; j < 16; ++j) {
                int col = 8 * j + qc2;
                float2 gA = *(const float2*)(giA + 256 + col);
                float2 gB = *(const float2*)(giB + 256 + col);
                float b0 = sbn[col], b1 = sbn[col + 1];
                accN[j][0] = tanh_f(gA.x + accR[j][0] * (accN[j][0] + b0));
                accN[j][1] = tanh_f(gA.y + accR[j][1] * (accN[j][1] + b1));
                accN[j][2] = tanh_f(gB.x + accR[j][2] * (accN[j][2] + b0));
                accN[j][3] = tanh_f(gB.y + accR[j][3] * (accN[j][3] + b1));
            }
            // ---- z gate (reuse accR) + h update + repack frags ----
#pragma unroll
            for (int j = 0; j < 16; ++j) { accR[j][0] = accR[j][1] = accR[j][2] = accR[j][3] = 0.f; }
            if (t) gh1_gemm(ah, Bs + (u32)(128 * WROWH), lane, accR);
#pragma unroll
            for (int s = 0; s < 8; ++s) {
#pragma unroll
                for (int half = 0; half < 2; ++half) {
                    int j = 2 * s + half;
                    int col = 8 * j + qc2;
                    int fa = 4 * s + 2 * half;
                    int fb = fa + 1;
                    float2 gA = *(const float2*)(giA + 128 + col);
                    float2 gB = *(const float2*)(giB + 128 + col);
                    if (aA) {
                        float z0 = sigm_f(accR[j][0] + gA.x);
                        float z1 = sigm_f(accR[j][1] + gA.y);
                        float h0 = (1.f - z0) * accN[j][0] + z0 * lofh(ah[fa]);
                        float h1 = (1.f - z1) * accN[j][1] + z1 * hifh(ah[fa]);
                        ah[fa] = pkh(h1, h0);
                    }
                    if (aB) {
                        float z2 = sigm_f(accR[j][2] + gB.x);
                        float z3 = sigm_f(accR[j][3] + gB.y);
                        float h2 = (1.f - z2) * accN[j][2] + z2 * lofh(ah[fb]);
                        float h3 = (1.f - z3) * accN[j][3] + z3 * hifh(ah[fb]);
                        ah[fb] = pkh(h3, h2);
                    }
                }
            }
        }
        // write back final h frags (fp16, 128 u16/row)
        u16* hA = g_hs + (size_t)iA * 128;
        u16* hB = g_hs + (size_t)iB * 128;
#pragma unroll
        for (int s = 0; s < 8; ++s) {
#pragma unroll
            for (int half = 0; half < 2; ++half) {
                int col = 8 * (2 * s + half) + qc2;
                int fa = 4 * s + 2 * half, fb = fa + 1;
                *(u32*)(hA + col) = ah[fa];
                *(u32*)(hB + col) = ah[fb];
            }
        }
    }
}

// ---------------- persistent final GEMM ----------------
__global__ void __launch_bounds__(256, 1) k_final_p(float* __restrict__ out) {
    extern __shared__ char sm[];
    int tid = threadIdx.x, lane = tid & 31;
    copy_w(sm, g_wself2, 128, tid);
    copy_wh(sm + 128 * WROW, g_wnhh, 128, tid);
    __syncthreads();
    u32 Bs = su32(sm);
    int qr = lane >> 2, qc2 = (lane & 3) * 2;
    while (true) {
        u32 gid;
        if (lane == 0) gid = atomicAdd(&g_wctr[2], 1);
        gid = __shfl_sync(0xFFFFFFFFu, gid, 0);
        if (gid >= NGRP) break;
        int iA = (int)gid * 16 + qr, iB = iA + 8;
        int nA = g_perm[iA], nB = g_perm[iB];
        float acc[16][4];
#pragma unroll
        for (int j = 0; j < 16; ++j) { acc[j][0] = acc[j][1] = acc[j][2] = acc[j][3] = 0.f; }
        {
            u32 ah[32], al[32];
            load_frags(g_xs + (size_t)nA * 256, g_xs + (size_t)nB * 256, qc2, ah, al);
            ga_gemm(ah, al, Bs, lane, acc);
        }
        {
            u32 ah[32];
            load_frags_h(g_hs + (size_t)iA * 128, g_hs + (size_t)iB * 128, qc2, ah);
            gh1_gemm(ah, Bs + (u32)(128 * WROW), lane, acc);
        }
        float* oA = out + (size_t)nA * 128;
        float* oB = out + (size_t)nB * 128;
#pragma unroll
        for (int j = 0; j < 16; ++j) {
            int col = 8 * j + qc2;
            *(float2*)(oA + col) = make_float2(acc[j][0], acc[j][1]);
            *(float2*)(oB + col) = make_float2(acc[j][2], acc[j][3]);
        }
    }
}

// ---------------- launch ----------------
extern "C" void kernel_launch(void* const* d_in, const int* in_sizes, int n_in,
                              void* d_out, int out_size) {
    const float* feat    = (const float*)d_in[0];
    const float* gamma   = (const float*)d_in[1];
    const float* beta    = (const float*)d_in[2];
    const float* W_ih    = (const float*)d_in[3];
    const float* W_hh    = (const float*)d_in[4];
    const float* b_ih    = (const float*)d_in[5];
    const float* b_hh    = (const float*)d_in[6];
    const float* W_self  = (const float*)d_in[7];
    const float* W_neigh = (const float*)d_in[8];
    const int*   src     = (const int*)d_in[9];
    const void*  mask    = (const void*)d_in[10];
    float* out = (float*)d_out;

    cudaFuncSetAttribute(k_gi_p,    cudaFuncAttributeMaxDynamicSharedMemorySize, SM_GI);
    cudaFuncSetAttribute(k_scan_p,  cudaFuncAttributeMaxDynamicSharedMemorySize, SM_SC);
    cudaFuncSetAttribute(k_final_p, cudaFuncAttributeMaxDynamicSharedMemorySize, SM_FN);

    k_detect<<<1, 256>>>((const unsigned char*)mask);
    k_zero<<<1, 32>>>();
    k_stats<<<RB, 128>>>(feat);
    k_deg<<<RB, 256>>>(mask);
    k_finalize<<<1, 128>>>(gamma, beta);
    k_scatter<<<RB, 256>>>(mask);
    k_normsplit<<<(NN * 32 + 255) / 256, 256>>>(feat);
    k_wsplit<<<64, 256>>>(W_ih, W_self);
    k_whalf<<<128, 256>>>(W_hh, W_neigh);
    k_gi_p<<<PGRID, 256, SM_GI>>>(b_ih, b_hh);
    k_scan_p<<<PGRID, 256, SM_SC>>>(src, b_hh);
    k_final_p<<<PGRID, 256, SM_FN>>>(out);
}

// round 17
// speedup vs baseline: 5.9439x; 1.2683x over previous
#include <cuda_runtime.h>
#include <math.h>

typedef unsigned int u32;
typedef unsigned short u16;

#define NN 200000
#define MD 12
#define RB ((NN + 255) / 256)         // 782
#define NGRP (NN / 16)                // 12500 row-groups of 16
#define PGRID 148

#define WROW 528                      // padded smem row: 264 u16 (bf16-split weights)
#define WROWH 272                     // padded smem row: 136 u16 (fp16 weights)
#define SM_GI (384 * WROW + 1536)     // W_ih + folded biases
#define SM_SC (384 * WROWH + 512 + 64)// W_hh fp16 + bhh_n + act
#define SM_FN (128 * WROW + 128 * WROWH) // W_self bf16split | W_neigh fp16

// ---------------- scratch (device globals: allocation-free) ----------------
__device__ __align__(256) u16 g_gih[(size_t)NN * 384 + 512]; // x@W_ih^T + biases (fp16, padded tail)
__device__ __align__(256) u16 g_xs[(size_t)NN * 256];     // x split [hi128|lo128] bf16
__device__ __align__(256) u16 g_hs[(size_t)NN * 128];     // final h (fp16, sorted order)
__device__ __align__(256) u16 g_wih2[384 * 256];          // W_ih bf16 split
__device__ __align__(256) u16 g_wself2[128 * 256];        // W_self bf16 split
__device__ __align__(256) u16 g_whhh[384 * 128];          // W_hh fp16
__device__ __align__(256) u16 g_wnhh[128 * 128];          // W_neigh fp16
__device__ float g_psum[RB * 128];
__device__ float g_psq [RB * 128];
__device__ float g_a[128], g_b[128];
__device__ int   g_cnt[MD + 1], g_cur[MD + 1], g_act[MD];
__device__ int   g_perm[NN];
__device__ int   g_mtype;
__device__ u32   g_wctr[4];

__device__ __forceinline__ float sigm_f(float x) {
    return __fdividef(1.0f, 1.0f + __expf(-x));
}
__device__ __forceinline__ float tanh_f(float x) {
    return 1.0f - __fdividef(2.0f, __expf(2.0f * x) + 1.0f);
}

__device__ __forceinline__ u32 bf_rn(float v, float& asf) {
    u32 u = __float_as_uint(v);
    u32 r = (u + 0x7FFFu + ((u >> 16) & 1u)) & 0xFFFF0000u;
    asf = __uint_as_float(r);
    return r >> 16;
}
// fp16x2 pack/unpack
__device__ __forceinline__ u32 pkh(float hi, float lo) {
    u32 d; asm("cvt.rn.f16x2.f32 %0, %1, %2;" : "=r"(d) : "f"(hi), "f"(lo)); return d;
}
__device__ __forceinline__ float lofh(u32 a) {
    float f;
    asm("{\n\t.reg .b16 l,h;\n\tmov.b32 {l,h}, %1;\n\tcvt.f32.f16 %0, l;\n\t}"
        : "=f"(f) : "r"(a));
    return f;
}
__device__ __forceinline__ float hifh(u32 a) {
    float f;
    asm("{\n\t.reg .b16 l,h;\n\tmov.b32 {l,h}, %1;\n\tcvt.f32.f16 %0, h;\n\t}"
        : "=f"(f) : "r"(a));
    return f;
}
__device__ __forceinline__ float2 upk2(u32 a) {
    float2 f;
    asm("{\n\t.reg .b16 l,h;\n\tmov.b32 {l,h}, %2;\n\tcvt.f32.f16 %0, l;\n\tcvt.f32.f16 %1, h;\n\t}"
        : "=f"(f.x), "=f"(f.y) : "r"(a));
    return f;
}

__device__ __forceinline__ u32 su32(const void* p) {
    return (u32)__cvta_generic_to_shared(p);
}
__device__ __forceinline__ void ldsm4(u32& r0, u32& r1, u32& r2, u32& r3, u32 a) {
    asm volatile("ldmatrix.sync.aligned.m8n8.x4.shared.b16 {%0,%1,%2,%3}, [%4];"
                 : "=r"(r0), "=r"(r1), "=r"(r2), "=r"(r3) : "r"(a));
}
__device__ __forceinline__ void mma_bf16(float* c, u32 a0, u32 a1, u32 a2, u32 a3,
                                         u32 b0, u32 b1) {
    asm volatile("mma.sync.aligned.m16n8k16.row.col.f32.bf16.bf16.f32 "
                 "{%0,%1,%2,%3}, {%4,%5,%6,%7}, {%8,%9}, {%0,%1,%2,%3};"
                 : "+f"(c[0]), "+f"(c[1]), "+f"(c[2]), "+f"(c[3])
                 : "r"(a0), "r"(a1), "r"(a2), "r"(a3), "r"(b0), "r"(b1));
}
__device__ __forceinline__ void mma_f16(float* c, u32 a0, u32 a1, u32 a2, u32 a3,
                                        u32 b0, u32 b1) {
    asm volatile("mma.sync.aligned.m16n8k16.row.col.f32.f16.f16.f32 "
                 "{%0,%1,%2,%3}, {%4,%5,%6,%7}, {%8,%9}, {%0,%1,%2,%3};"
                 : "+f"(c[0]), "+f"(c[1]), "+f"(c[2]), "+f"(c[3])
                 : "r"(a0), "r"(a1), "r"(a2), "r"(a3), "r"(b0), "r"(b1));
}
__device__ __forceinline__ void pf_l2(const void* p) {
    asm volatile("prefetch.global.L2 [%0];" :: "l"(p));
}

// bf16 split GEMM (3 products) — x-side; B rows are 256 u16 wide (WROW stride)
__device__ __forceinline__ void ga_gemm(const u32* ah, const u32* al, u32 BsG, int lane,
                                        float acc[16][4]) {
    u32 brow = BsG + (u32)(((((lane >> 4) << 3) + (lane & 7)) * WROW) + ((lane >> 3) & 1) * 16);
#pragma unroll
    for (int s = 0; s < 8; ++s) {
        u32 a0 = ah[4*s], a1 = ah[4*s+1], a2 = ah[4*s+2], a3 = ah[4*s+3];
        u32 l0 = al[4*s], l1 = al[4*s+1], l2 = al[4*s+2], l3 = al[4*s+3];
#pragma unroll
        for (int j2 = 0; j2 < 8; ++j2) {
            u32 base = brow + (u32)(j2 * 16 * WROW + 32 * s);
            u32 b0, b1, b2, b3, c0, c1, c2, c3;
            ldsm4(b0, b1, b2, b3, base);
            ldsm4(c0, c1, c2, c3, base + 256);
            mma_bf16(acc[2*j2],   a0, a1, a2, a3, b0, b1);
            mma_bf16(acc[2*j2+1], a0, a1, a2, a3, b2, b3);
            mma_bf16(acc[2*j2],   l0, l1, l2, l3, b0, b1);
            mma_bf16(acc[2*j2+1], l0, l1, l2, l3, b2, b3);
            mma_bf16(acc[2*j2],   a0, a1, a2, a3, c0, c1);
            mma_bf16(acc[2*j2+1], a0, a1, a2, a3, c2, c3);
        }
    }
}

// fp16 single-product GEMM — h-side; B rows are 128 u16 wide (WROWH stride)
__device__ __forceinline__ void gh1_gemm(const u32* ah, u32 BsG, int lane,
                                         float acc[16][4]) {
    u32 brow = BsG + (u32)(((((lane >> 4) << 3) + (lane & 7)) * WROWH) + ((lane >> 3) & 1) * 16);
#pragma unroll
    for (int s = 0; s < 8; ++s) {
        u32 a0 = ah[4*s], a1 = ah[4*s+1], a2 = ah[4*s+2], a3 = ah[4*s+3];
#pragma unroll
        for (int j2 = 0; j2 < 8; ++j2) {
            u32 base = brow + (u32)(j2 * 16 * WROWH + 32 * s);
            u32 b0, b1, b2, b3;
            ldsm4(b0, b1, b2, b3, base);
            mma_f16(acc[2*j2],   a0, a1, a2, a3, b0, b1);
            mma_f16(acc[2*j2+1], a0, a1, a2, a3, b2, b3);
        }
    }
}

__device__ __forceinline__ void load_frags(const u16* rA, const u16* rB, int qc2,
                                           u32* ah, u32* al) {
#pragma unroll
    for (int s = 0; s < 8; ++s) {
        ah[4*s]   = *(const u32*)(rA + 16*s + qc2);
        ah[4*s+1] = *(const u32*)(rB + 16*s + qc2);
        ah[4*s+2] = *(const u32*)(rA + 16*s + 8 + qc2);
        ah[4*s+3] = *(const u32*)(rB + 16*s + 8 + qc2);
        al[4*s]   = *(const u32*)(rA + 128 + 16*s + qc2);
        al[4*s+1] = *(const u32*)(rB + 128 + 16*s + qc2);
        al[4*s+2] = *(const u32*)(rA + 128 + 16*s + 8 + qc2);
        al[4*s+3] = *(const u32*)(rB + 128 + 16*s + 8 + qc2);
    }
}
// fp16 h rows: 128 u16 wide
__device__ __forceinline__ void load_frags_h(const u16* rA, const u16* rB, int qc2, u32* ah) {
#pragma unroll
    for (int s = 0; s < 8; ++s) {
        ah[4*s]   = *(const u32*)(rA + 16*s + qc2);
        ah[4*s+1] = *(const u32*)(rB + 16*s + qc2);
        ah[4*s+2] = *(const u32*)(rA + 16*s + 8 + qc2);
        ah[4*s+3] = *(const u32*)(rB + 16*s + 8 + qc2);
    }
}

__device__ __forceinline__ void copy_w(char* sm, const u16* w, int rows, int tid) {
    for (int idx = tid; idx < rows * 32; idx += 256) {
        int r = idx >> 5, c = idx & 31;
        uint4 v = ((const uint4*)w)[idx];
        *(uint4*)(sm + r * WROW + c * 16) = v;
    }
}
__device__ __forceinline__ void copy_wh(char* sm, const u16* w, int rows, int tid) {
    for (int idx = tid; idx < rows * 16; idx += 256) {
        int r = idx >> 4, c = idx & 15;
        uint4 v = ((const uint4*)w)[idx];
        *(uint4*)(sm + r * WROWH + c * 16) = v;
    }
}

// ---------------- mask dtype detection / setup (verified R6..R15) ----------------
__global__ void k_detect(const unsigned char* __restrict__ m) {
    __shared__ int has3F, nzNot0, nz0;
    if (threadIdx.x == 0) { has3F = 0; nzNot0 = 0; nz0 = 0; }
    __syncthreads();
    for (int i = threadIdx.x; i < 16384; i += 256) {
        unsigned char b = m[i];
        if (b == 0x3F) atomicOr(&has3F, 1);
        if (b != 0 && (i & 3) != 0) atomicOr(&nzNot0, 1);
        if (b != 0 && (i & 3) == 0) atomicOr(&nz0, 1);
    }
    __syncthreads();
    if (threadIdx.x == 0) {
        int ty;
        if (has3F && nz0) ty = 3;
        else if (has3F)   ty = 2;
        else if (nzNot0)  ty = 0;
        else              ty = 1;
        g_mtype = ty;
    }
}

__device__ __forceinline__ int deg_any(const void* m, int n) {
    int ty = g_mtype;
    int d = 0;
    if (ty == 1) {
        const int* p = (const int*)m + (size_t)n * MD;
#pragma unroll
        for (int j = 0; j < MD; ++j) d += (p[j] != 0);
    } else if (ty == 0) {
        const unsigned char* p = (const unsigned char*)m + (size_t)n * MD;
#pragma unroll
        for (int j = 0; j < MD; ++j) d += (p[j] != 0);
    } else if (ty == 2) {
        const float* p = (const float*)m + (size_t)n * MD;
#pragma unroll
        for (int j = 0; j < MD; ++j) d += (p[j] != 0.0f);
    } else {
        const u16* p = (const u16*)m + (size_t)n * MD;
#pragma unroll
        for (int j = 0; j < MD; ++j) d += ((p[j] & 0x7FFF) != 0);
    }
    return d;
}

__global__ void k_zero() {
    int t = threadIdx.x;
    if (t <= MD) g_cnt[t] = 0;
    if (t < 4) g_wctr[t] = 0;
}

__global__ void k_stats(const float* __restrict__ feat) {
    int col = threadIdx.x;
    int r0 = blockIdx.x * 256;
    int rend = min(r0 + 256, NN);
    float s = 0.f, q = 0.f;
    for (int r = r0; r < rend; ++r) {
        float v = feat[(size_t)r * 128 + col];
        s += v; q += v * v;
    }
    g_psum[blockIdx.x * 128 + col] = s;
    g_psq [blockIdx.x * 128 + col] = q;
}

__global__ void k_deg(const void* __restrict__ mask) {
    __shared__ int c[MD + 1];
    int tid = threadIdx.x;
    if (tid <= MD) c[tid] = 0;
    __syncthreads();
    int n = blockIdx.x * 256 + tid;
    if (n < NN) atomicAdd(&c[deg_any(mask, n)], 1);
    __syncthreads();
    if (tid <= MD && c[tid] > 0) atomicAdd(&g_cnt[tid], c[tid]);
}

__global__ void k_finalize(const float* __restrict__ gamma, const float* __restrict__ beta) {
    int t = threadIdx.x;
    float s = 0.f, q = 0.f;
    for (int b = 0; b < RB; ++b) { s += g_psum[b * 128 + t]; q += g_psq[b * 128 + t]; }
    float mu = s * (1.0f / NN);
    float var = q * (1.0f / NN) - mu * mu;
    float rs = rsqrtf(var + 1e-5f);
    float a = rs * gamma[t];
    g_a[t] = a;
    g_b[t] = beta[t] - mu * a;
    if (t == 0) {
        int suf = 0;
        for (int d = MD; d >= 0; --d) { g_cur[d] = suf; suf += g_cnt[d]; }
        for (int sdx = 0; sdx < MD; ++sdx) g_act[sdx] = g_cur[sdx];
    }
}

__global__ void k_scatter(const void* __restrict__ mask) {
    int n = blockIdx.x * 256 + threadIdx.x;
    if (n >= NN) return;
    int pos = atomicAdd(&g_cur[deg_any(mask, n)], 1);
    g_perm[pos] = n;
}

__global__ void k_normsplit(const float* __restrict__ feat) {
    int i = blockIdx.x * 256 + threadIdx.x;
    if (i >= NN * 32) return;
    float4 v = ((const float4*)feat)[i];
    int row = i >> 5;
    int c = (i & 31) << 2;
    float f0 = v.x * g_a[c + 0] + g_b[c + 0];
    float f1 = v.y * g_a[c + 1] + g_b[c + 1];
    float f2 = v.z * g_a[c + 2] + g_b[c + 2];
    float f3 = v.w * g_a[c + 3] + g_b[c + 3];
    float h0, h1, h2, h3, d0;
    u32 a0 = bf_rn(f0, h0), a1 = bf_rn(f1, h1), a2 = bf_rn(f2, h2), a3 = bf_rn(f3, h3);
    u32 b0 = bf_rn(f0 - h0, d0), b1 = bf_rn(f1 - h1, d0), b2 = bf_rn(f2 - h2, d0), b3 = bf_rn(f3 - h3, d0);
    u16* dst = g_xs + (size_t)row * 256;
    *(uint2*)(dst + c)       = make_uint2(a0 | (a1 << 16), a2 | (a3 << 16));
    *(uint2*)(dst + 128 + c) = make_uint2(b0 | (b1 << 16), b2 | (b3 << 16));
}

// bf16-split conversion: 512 rows (384 Wih, 128 Wself)
__global__ void k_wsplit(const float* __restrict__ wih, const float* __restrict__ wself) {
    int i = blockIdx.x * 256 + threadIdx.x;
    if (i >= 512 * 32) return;
    int row = i >> 5;
    int c = (i & 31) << 2;
    const float* src;
    u16* dst;
    if (row < 384) { src = wih + (size_t)row * 128;           dst = g_wih2 + (size_t)row * 256; }
    else           { src = wself + (size_t)(row - 384) * 128; dst = g_wself2 + (size_t)(row - 384) * 256; }
    float4 v = *(const float4*)(src + c);
    float h0, h1, h2, h3, dm;
    u32 a0 = bf_rn(v.x, h0), a1 = bf_rn(v.y, h1), a2 = bf_rn(v.z, h2), a3 = bf_rn(v.w, h3);
    u32 b0 = bf_rn(v.x - h0, dm), b1 = bf_rn(v.y - h1, dm), b2 = bf_rn(v.z - h2, dm), b3 = bf_rn(v.w - h3, dm);
    *(uint2*)(dst + c)       = make_uint2(a0 | (a1 << 16), a2 | (a3 << 16));
    *(uint2*)(dst + 128 + c) = make_uint2(b0 | (b1 << 16), b2 | (b3 << 16));
}

// fp16 conversion: 512 rows (384 Whh, 128 Wneigh), one thread per float2
__global__ void k_whalf(const float* __restrict__ whh, const float* __restrict__ wneigh) {
    int i = blockIdx.x * 256 + threadIdx.x;
    if (i >= 512 * 64) return;
    int row = i >> 6;
    int c2 = (i & 63) * 2;
    const float* s;
    u16* d;
    if (row < 384) { s = whh + (size_t)row * 128;            d = g_whhh + (size_t)row * 128; }
    else           { s = wneigh + (size_t)(row - 384) * 128; d = g_wnhh + (size_t)(row - 384) * 128; }
    float2 v = *(const float2*)(s + c2);
    *(u32*)(d + c2) = pkh(v.y, v.x);
}

// ---------------- persistent gi GEMM: g_gih = fp16(x @ W_ih^T + folded biases) ----------------
__global__ void __launch_bounds__(256, 1) k_gi_p(const float* __restrict__ bih,
                                                 const float* __restrict__ bhh) {
    extern __shared__ char sm[];
    int tid = threadIdx.x, lane = tid & 31;
    copy_w(sm, g_wih2, 384, tid);
    float* sb = (float*)(sm + 384 * WROW);
    for (int j = tid; j < 384; j += 256)
        sb[j] = bih[j] + (j < 256 ? bhh[j] : 0.f);
    __syncthreads();
    u32 Bs = su32(sm);
    int qr = lane >> 2, qc2 = (lane & 3) * 2;
    while (true) {
        u32 gid;
        if (lane == 0) gid = atomicAdd(&g_wctr[0], 1);
        gid = __shfl_sync(0xFFFFFFFFu, gid, 0);
        if (gid >= NGRP) break;
        int iA = gid * 16 + qr, iB = iA + 8;
        u32 ah[32], al[32];
        load_frags(g_xs + (size_t)iA * 256, g_xs + (size_t)iB * 256, qc2, ah, al);
        u16* oA = g_gih + (size_t)iA * 384;
        u16* oB = g_gih + (size_t)iB * 384;
#pragma unroll 1
        for (int g = 0; g < 3; ++g) {
            float acc[16][4];
#pragma unroll
            for (int j = 0; j < 16; ++j) { acc[j][0] = acc[j][1] = acc[j][2] = acc[j][3] = 0.f; }
            ga_gemm(ah, al, Bs + (u32)(g * 128 * WROW), lane, acc);
#pragma unroll
            for (int j = 0; j < 16; ++j) {
                int col = g * 128 + 8 * j + qc2;
                float b0 = sb[g * 128 + 8 * j + qc2], b1 = sb[g * 128 + 8 * j + qc2 + 1];
                *(u32*)(oA + col) = pkh(acc[j][1] + b1, acc[j][0] + b0);
                *(u32*)(oB + col) = pkh(acc[j][3] + b1, acc[j][2] + b0);
            }
        }
    }
}

// ---------------- persistent 12-step GRU scan (fp16 h frags, fp16 gi table) ----------------
__global__ void __launch_bounds__(256, 1) k_scan_p(const int* __restrict__ src,
                                                   const float* __restrict__ bhh) {
    extern __shared__ char sm[];
    int tid = threadIdx.x, lane = tid & 31;
    copy_wh(sm, g_whhh, 384, tid);
    float* sbn = (float*)(sm + 384 * WROWH);
    int* sact = (int*)(sbn + 128);
    if (tid < 128) sbn[tid] = bhh[256 + tid];
    if (tid < MD) sact[tid] = g_act[tid];
    __syncthreads();
    u32 Bs = su32(sm);
    int qr = lane >> 2, qc2 = (lane & 3) * 2;
    int pfo = (lane & 3) * 192;           // 4 lanes x [off, off+128) cover the 768B row
    while (true) {
        u32 gid;
        if (lane == 0) gid = atomicAdd(&g_wctr[1], 1);
        gid = __shfl_sync(0xFFFFFFFFu, gid, 0);
        if (gid >= NGRP) break;
        int i0 = (int)gid * 16;
        int iA = i0 + qr, iB = iA + 8;
        int nA = g_perm[iA], nB = g_perm[iB];
        const int* sAp = src + (size_t)nA * MD;
        const int* sBp = src + (size_t)nB * MD;
        if (sact[0] > i0) {
            const char* qA = (const char*)(g_gih + (size_t)__ldg(sAp) * 384) + pfo;
            const char* qB = (const char*)(g_gih + (size_t)__ldg(sBp) * 384) + pfo;
            pf_l2(qA); pf_l2(qA + 128);
            pf_l2(qB); pf_l2(qB + 128);
        }
        u32 ah[32];                 // h state as fp16 mma A-fragments
#pragma unroll
        for (int k = 0; k < 32; ++k) ah[k] = 0u;
#pragma unroll 1
        for (int t = 0; t < MD; ++t) {
            int actT = sact[t];
            if (actT <= i0) break;
            bool aA = iA < actT, aB = iB < actT;
            int sA = __ldg(sAp + t), sB = __ldg(sBp + t);
            const u16* giA = g_gih + (size_t)sA * 384;
            const u16* giB = g_gih + (size_t)sB * 384;
            if (t + 1 < MD && sact[t + 1] > i0) {
                const char* qA = (const char*)(g_gih + (size_t)__ldg(sAp + t + 1) * 384) + pfo;
                const char* qB = (const char*)(g_gih + (size_t)__ldg(sBp + t + 1) * 384) + pfo;
                pf_l2(qA); pf_l2(qA + 128);
                pf_l2(qB); pf_l2(qB + 128);
            }
            // ---- r gate ----
            float accR[16][4];
#pragma unroll
            for (int j = 0; j < 16; ++j) { accR[j][0] = accR[j][1] = accR[j][2] = accR[j][3] = 0.f; }
            if (t) gh1_gemm(ah, Bs, lane, accR);
#pragma unroll
            for (int j = 0; j < 16; ++j) {
                int col = 8 * j + qc2;
                float2 gA = upk2(*(const u32*)(giA + col));
                float2 gB = upk2(*(const u32*)(giB + col));
                accR[j][0] = sigm_f(accR[j][0] + gA.x);
                accR[j][1] = sigm_f(accR[j][1] + gA.y);
                accR[j][2] = sigm_f(accR[j][2] + gB.x);
                accR[j][3] = sigm_f(accR[j][3] + gB.y);
            }
            // ---- n gate ----
            float accN[16][4];
#pragma unroll
            for (int j = 0; j < 16; ++j) { accN[j][0] = accN[j][1] = accN[j][2] = accN[j][3] = 0.f; }
            if (t) gh1_gemm(ah, Bs + (u32)(256 * WROWH), lane, accN);
#pragma unroll
            for (int j = 0; j < 16; ++j) {
                int col = 8 * j + qc2;
                float2 gA = upk2(*(const u32*)(giA + 256 + col));
                float2 gB = upk2(*(const u32*)(giB + 256 + col));
                float b0 = sbn[col], b1 = sbn[col + 1];
                accN[j][0] = tanh_f(gA.x + accR[j][0] * (accN[j][0] + b0));
                accN[j][1] = tanh_f(gA.y + accR[j][1] * (accN[j][1] + b1));
                accN[j][2] = tanh_f(gB.x + accR[j][2] * (accN[j][2] + b0));
                accN[j][3] = tanh_f(gB.y + accR[j][3] * (accN[j][3] + b1));
            }
            // ---- z gate (reuse accR) + h update + repack frags ----
#pragma unroll
            for (int j = 0; j < 16; ++j) { accR[j][0] = accR[j][1] = accR[j][2] = accR[j][3] = 0.f; }
            if (t) gh1_gemm(ah, Bs + (u32)(128 * WROWH), lane, accR);
#pragma unroll
            for (int s = 0; s < 8; ++s) {
#pragma unroll
                for (int half = 0; half < 2; ++half) {
                    int j = 2 * s + half;
                    int col = 8 * j + qc2;
                    int fa = 4 * s + 2 * half;
                    int fb = fa + 1;
                    float2 gA = upk2(*(const u32*)(giA + 128 + col));
                    float2 gB = upk2(*(const u32*)(giB + 128 + col));
                    if (aA) {
                        float z0 = sigm_f(accR[j][0] + gA.x);
                        float z1 = sigm_f(accR[j][1] + gA.y);
                        float h0 = (1.f - z0) * accN[j][0] + z0 * lofh(ah[fa]);
                        float h1 = (1.f - z1) * accN[j][1] + z1 * hifh(ah[fa]);
                        ah[fa] = pkh(h1, h0);
                    }
                    if (aB) {
                        float z2 = sigm_f(accR[j][2] + gB.x);
                        float z3 = sigm_f(accR[j][3] + gB.y);
                        float h2 = (1.f - z2) * accN[j][2] + z2 * lofh(ah[fb]);
                        float h3 = (1.f - z3) * accN[j][3] + z3 * hifh(ah[fb]);
                        ah[fb] = pkh(h3, h2);
                    }
                }
            }
        }
        // write back final h frags (fp16, 128 u16/row)
        u16* hA = g_hs + (size_t)iA * 128;
        u16* hB = g_hs + (size_t)iB * 128;
#pragma unroll
        for (int s = 0; s < 8; ++s) {
#pragma unroll
            for (int half = 0; half < 2; ++half) {
                int col = 8 * (2 * s + half) + qc2;
                int fa = 4 * s + 2 * half, fb = fa + 1;
                *(u32*)(hA + col) = ah[fa];
                *(u32*)(hB + col) = ah[fb];
            }
        }
    }
}

// ---------------- persistent final GEMM ----------------
__global__ void __launch_bounds__(256, 1) k_final_p(float* __restrict__ out) {
    extern __shared__ char sm[];
    int tid = threadIdx.x, lane = tid & 31;
    copy_w(sm, g_wself2, 128, tid);
    copy_wh(sm + 128 * WROW, g_wnhh, 128, tid);
    __syncthreads();
    u32 Bs = su32(sm);
    int qr = lane >> 2, qc2 = (lane & 3) * 2;
    while (true) {
        u32 gid;
        if (lane == 0) gid = atomicAdd(&g_wctr[2], 1);
        gid = __shfl_sync(0xFFFFFFFFu, gid, 0);
        if (gid >= NGRP) break;
        int iA = (int)gid * 16 + qr, iB = iA + 8;
        int nA = g_perm[iA], nB = g_perm[iB];
        float acc[16][4];
#pragma unroll
        for (int j = 0; j < 16; ++j) { acc[j][0] = acc[j][1] = acc[j][2] = acc[j][3] = 0.f; }
        {
            u32 ah[32], al[32];
            load_frags(g_xs + (size_t)nA * 256, g_xs + (size_t)nB * 256, qc2, ah, al);
            ga_gemm(ah, al, Bs, lane, acc);
        }
        {
            u32 ah[32];
            load_frags_h(g_hs + (size_t)iA * 128, g_hs + (size_t)iB * 128, qc2, ah);
            gh1_gemm(ah, Bs + (u32)(128 * WROW), lane, acc);
        }
        float* oA = out + (size_t)nA * 128;
        float* oB = out + (size_t)nB * 128;
#pragma unroll
        for (int j = 0; j < 16; ++j) {
            int col = 8 * j + qc2;
            *(float2*)(oA + col) = make_float2(acc[j][0], acc[j][1]);
            *(float2*)(oB + col) = make_float2(acc[j][2], acc[j][3]);
        }
    }
}

// ---------------- launch ----------------
extern "C" void kernel_launch(void* const* d_in, const int* in_sizes, int n_in,
                              void* d_out, int out_size) {
    const float* feat    = (const float*)d_in[0];
    const float* gamma   = (const float*)d_in[1];
    const float* beta    = (const float*)d_in[2];
    const float* W_ih    = (const float*)d_in[3];
    const float* W_hh    = (const float*)d_in[4];
    const float* b_ih    = (const float*)d_in[5];
    const float* b_hh    = (const float*)d_in[6];
    const float* W_self  = (const float*)d_in[7];
    const float* W_neigh = (const float*)d_in[8];
    const int*   src     = (const int*)d_in[9];
    const void*  mask    = (const void*)d_in[10];
    float* out = (float*)d_out;

    cudaFuncSetAttribute(k_gi_p,    cudaFuncAttributeMaxDynamicSharedMemorySize, SM_GI);
    cudaFuncSetAttribute(k_scan_p,  cudaFuncAttributeMaxDynamicSharedMemorySize, SM_SC);
    cudaFuncSetAttribute(k_final_p, cudaFuncAttributeMaxDynamicSharedMemorySize, SM_FN);

    k_detect<<<1, 256>>>((const unsigned char*)mask);
    k_zero<<<1, 32>>>();
    k_stats<<<RB, 128>>>(feat);
    k_deg<<<RB, 256>>>(mask);
    k_finalize<<<1, 128>>>(gamma, beta);
    k_scatter<<<RB, 256>>>(mask);
    k_normsplit<<<(NN * 32 + 255) / 256, 256>>>(feat);
    k_wsplit<<<64, 256>>>(W_ih, W_self);
    k_whalf<<<128, 256>>>(W_hh, W_neigh);
    k_gi_p<<<PGRID, 256, SM_GI>>>(b_ih, b_hh);
    k_scan_p<<<PGRID, 256, SM_SC>>>(src, b_hh);
    k_final_p<<<PGRID, 256, SM_FN>>>(out);
}